// round 4
// baseline (speedup 1.0000x reference)
#include <cuda_runtime.h>
#include <cuda_bf16.h>
#include <math.h>

// Problem constants
#define B_  2
#define S_  2048
#define H_  1024
#define NH_ 16
#define D_  64
#define ROWS_ (B_*S_)        // 4096
#define EPS_ 1.1920929e-07f
#define QSCALE_ (0.125f * 1.4426950408889634f)   // (1/sqrt(D)) * log2(e)

// ---------------- scratch -------------------------------------------------------------
__device__ float g_qkv[(size_t)ROWS_ * 3 * H_];
__device__ float g_q[(size_t)B_*NH_*S_*D_];
__device__ float g_k[(size_t)B_*NH_*S_*D_];
__device__ float g_v[(size_t)B_*NH_*S_*D_];
__device__ float g_attn[(size_t)ROWS_ * H_];
__device__ float g_cos[S_*32];
__device__ float g_sin[S_*32];

// ---------------- helpers -------------------------------------------------------------
__device__ __forceinline__ unsigned f2tf32(float f) {
    unsigned u;
    asm("cvt.rna.tf32.f32 %0, %1;" : "=r"(u) : "f"(f));
    return u;
}
__device__ __forceinline__ float ex2(float x) {
    float r;
    asm("ex2.approx.f32 %0, %1;" : "=f"(r) : "f"(x));
    return r;
}
__device__ __forceinline__ void mma_tf32(float c[4], const unsigned a[4], const unsigned b[2]) {
    asm volatile(
        "mma.sync.aligned.m16n8k8.row.col.f32.tf32.tf32.f32 "
        "{%0,%1,%2,%3}, {%4,%5,%6,%7}, {%8,%9}, {%0,%1,%2,%3};"
        : "+f"(c[0]), "+f"(c[1]), "+f"(c[2]), "+f"(c[3])
        : "r"(a[0]), "r"(a[1]), "r"(a[2]), "r"(a[3]), "r"(b[0]), "r"(b[1]));
}

// ---------------- RoPE table ----------------------------------------------------------
__global__ void rope_table_kernel() {
    int idx = blockIdx.x * blockDim.x + threadIdx.x;
    if (idx >= S_*32) return;
    int s = idx >> 5, j = idx & 31;
    double invf = pow(1.0e-4, (double)j / 32.0);
    float f = (float)s * (float)invf;
    double sn, cs;
    sincos((double)f, &sn, &cs);
    g_cos[idx] = (float)cs;
    g_sin[idx] = (float)sn;
}

// ---------------- tf32 GEMM: C[M,N] = A[M,K] * B[N,K]^T -------------------------------
// 128x128 tile, BK=16, 256 thr = 8 warps (4m x 2n), warp tile 32x64.
// Pair-permuted k layout, row stride 40. Double-buffered, register-staged prefetch.
// __launch_bounds__(256,2) is load-bearing: forces <=128 regs so 2 CTAs/SM coexist.
#define GSTR 40
#define GEMM_SMEM_BYTES (4*128*GSTR*4)   // 2 mats x 2 stages = 80KB

__global__ __launch_bounds__(256, 2)
void gemm_v2(const float* __restrict__ A, const float* __restrict__ Bm,
             float* __restrict__ C, int M, int N, int K) {
    extern __shared__ unsigned smg[];
    unsigned* As = smg;                      // [2][128][GSTR]
    unsigned* Bs = smg + 2*128*GSTR;

    const int tid  = threadIdx.x;
    const int lane = tid & 31;
    const int wid  = tid >> 5;
    const int gr   = lane >> 2;
    const int gc   = lane & 3;
    const int bm = blockIdx.y * 128;
    const int bn = blockIdx.x * 128;
    const int wm = (wid >> 1) * 32;
    const int wn = (wid & 1) * 64;

    const int lrow = tid >> 1;               // 0..127
    const int lg   = tid & 1;                // k-subgroup
    const float* Ag = A  + (size_t)(bm + lrow) * K + lg*8;
    const float* Bg = Bm + (size_t)(bn + lrow) * K + lg*8;

    float4 ra0, ra1, rb0, rb1;
    float acc[2][8][4];
#pragma unroll
    for (int mi = 0; mi < 2; mi++)
#pragma unroll
        for (int ni = 0; ni < 8; ni++)
#pragma unroll
            for (int j = 0; j < 4; j++) acc[mi][ni][j] = 0.f;

    ra0 = *(const float4*)(Ag);  ra1 = *(const float4*)(Ag + 4);
    rb0 = *(const float4*)(Bg);  rb1 = *(const float4*)(Bg + 4);
    {
        unsigned* da = &As[lrow*GSTR + lg*8];
        da[0]=f2tf32(ra0.x); da[2]=f2tf32(ra0.y); da[4]=f2tf32(ra0.z); da[6]=f2tf32(ra0.w);
        da[1]=f2tf32(ra1.x); da[3]=f2tf32(ra1.y); da[5]=f2tf32(ra1.z); da[7]=f2tf32(ra1.w);
        unsigned* db = &Bs[lrow*GSTR + lg*8];
        db[0]=f2tf32(rb0.x); db[2]=f2tf32(rb0.y); db[4]=f2tf32(rb0.z); db[6]=f2tf32(rb0.w);
        db[1]=f2tf32(rb1.x); db[3]=f2tf32(rb1.y); db[5]=f2tf32(rb1.z); db[7]=f2tf32(rb1.w);
    }
    __syncthreads();

    const int T = K >> 4;
    for (int t = 0; t < T; t++) {
        const int cur = t & 1;
        if (t + 1 < T) {
            int k0 = (t+1) << 4;
            ra0 = *(const float4*)(Ag + k0);  ra1 = *(const float4*)(Ag + k0 + 4);
            rb0 = *(const float4*)(Bg + k0);  rb1 = *(const float4*)(Bg + k0 + 4);
        }
        const unsigned* Ab = &As[cur*128*GSTR];
        const unsigned* Bb = &Bs[cur*128*GSTR];
#pragma unroll
        for (int ks = 0; ks < 2; ks++) {
            unsigned a[2][4];
#pragma unroll
            for (int mi = 0; mi < 2; mi++) {
                uint2 lo = *(const uint2*)&Ab[(wm + mi*16 + gr)*GSTR + ks*8 + 2*gc];
                uint2 hi = *(const uint2*)&Ab[(wm + mi*16 + 8 + gr)*GSTR + ks*8 + 2*gc];
                a[mi][0] = lo.x; a[mi][1] = hi.x; a[mi][2] = lo.y; a[mi][3] = hi.y;
            }
#pragma unroll
            for (int ni = 0; ni < 8; ni++) {
                uint2 bb = *(const uint2*)&Bb[(wn + ni*8 + gr)*GSTR + ks*8 + 2*gc];
                unsigned b[2] = {bb.x, bb.y};
                mma_tf32(acc[0][ni], a[0], b);
                mma_tf32(acc[1][ni], a[1], b);
            }
        }
        if (t + 1 < T) {
            int nst = (t+1) & 1;
            unsigned* da = &As[nst*128*GSTR + lrow*GSTR + lg*8];
            da[0]=f2tf32(ra0.x); da[2]=f2tf32(ra0.y); da[4]=f2tf32(ra0.z); da[6]=f2tf32(ra0.w);
            da[1]=f2tf32(ra1.x); da[3]=f2tf32(ra1.y); da[5]=f2tf32(ra1.z); da[7]=f2tf32(ra1.w);
            unsigned* db = &Bs[nst*128*GSTR + lrow*GSTR + lg*8];
            db[0]=f2tf32(rb0.x); db[2]=f2tf32(rb0.y); db[4]=f2tf32(rb0.z); db[6]=f2tf32(rb0.w);
            db[1]=f2tf32(rb1.x); db[3]=f2tf32(rb1.y); db[5]=f2tf32(rb1.z); db[7]=f2tf32(rb1.w);
        }
        __syncthreads();
    }

#pragma unroll
    for (int mi = 0; mi < 2; mi++) {
        int m0 = bm + wm + mi*16 + gr;
#pragma unroll
        for (int ni = 0; ni < 8; ni++) {
            int n = bn + wn + ni*8 + 2*gc;
            *(float2*)(C + (size_t)m0 * N + n)       = make_float2(acc[mi][ni][0], acc[mi][ni][1]);
            *(float2*)(C + (size_t)(m0 + 8) * N + n) = make_float2(acc[mi][ni][2], acc[mi][ni][3]);
        }
    }
}

// ---------------- prep: RMSNorm + RoPE (q pre-scaled), lambda-mix, relayout -----------
__global__ void prep_kernel(const float* __restrict__ ve, const float* __restrict__ lambdas) {
    int gtid = blockIdx.x * blockDim.x + threadIdx.x;
    int warp = gtid >> 5;
    int lane = gtid & 31;
    if (warp >= B_*S_*NH_) return;
    int h = warp % NH_;
    int s = (warp / NH_) % S_;
    int b = warp / (NH_ * S_);

    const float* row = g_qkv + (size_t)(b*S_ + s) * (3*H_);
    float q1 = row[h*64 + lane],          q2 = row[h*64 + 32 + lane];
    float k1 = row[H_ + h*64 + lane],     k2 = row[H_ + h*64 + 32 + lane];
    float v1 = row[2*H_ + h*64 + lane],   v2 = row[2*H_ + h*64 + 32 + lane];

    float sq = q1*q1 + q2*q2;
    float sk = k1*k1 + k2*k2;
#pragma unroll
    for (int o = 16; o; o >>= 1) {
        sq += __shfl_xor_sync(0xffffffffu, sq, o);
        sk += __shfl_xor_sync(0xffffffffu, sk, o);
    }
    float rq = rsqrtf(sq * (1.f/64.f) + EPS_);
    float rk = rsqrtf(sk * (1.f/64.f) + EPS_);
    q1 *= rq; q2 *= rq; k1 *= rk; k2 *= rk;

    float c  = g_cos[s*32 + lane];
    float sn = g_sin[s*32 + lane];
    float qo1 = (q1*c + q2*sn) * QSCALE_;    // fold 1/sqrt(D)*log2(e) into Q
    float qo2 = (q2*c - q1*sn) * QSCALE_;
    float ko1 = k1*c + k2*sn, ko2 = k2*c - k1*sn;

    float l0 = lambdas[0], l1 = lambdas[1];
    const float* verow = ve + (size_t)(b*S_ + s) * H_ + h*64;
    float vo1 = l0*v1 + l1*verow[lane];
    float vo2 = l0*v2 + l1*verow[32 + lane];

    size_t o = ((size_t)(b*NH_ + h) * S_ + s) * 64 + lane;
    g_q[o]    = __uint_as_float(f2tf32(qo1));
    g_q[o+32] = __uint_as_float(f2tf32(qo2));
    g_k[o]    = __uint_as_float(f2tf32(ko1));
    g_k[o+32] = __uint_as_float(f2tf32(ko2));
    g_v[o]    = __uint_as_float(f2tf32(vo1));
    g_v[o+32] = __uint_as_float(f2tf32(vo2));
}

// ---------------- flash attention v3 --------------------------------------------------
// BM=128, BN=64, 256 thr = 8 warps; warp w owns q rows [16w,16w+16).
// smem: QP[128][72] (Q pair-permuted, aliased by P), Ks[64][72] (pair-permuted),
//       Vt[64][72] (V TRANSPOSED [d][n], n pair-permuted -> PV b-frag = 1 LDS.64).
// Scores arrive pre-scaled in log2 domain (Q carries 0.125*log2e); softmax uses ex2.
#define FSTR 72
#define FLASH_SMEM_BYTES ((128*FSTR + 64*FSTR + 64*FSTR)*4)   // 73728

__global__ __launch_bounds__(256)
void flash_v3() {
    extern __shared__ float sm[];
    float* QP = sm;                     // 128 x FSTR
    float* Ks = sm + 128*FSTR;          // 64 x FSTR
    float* Vt = Ks + 64*FSTR;           // 64 x FSTR  (row = d, col = n pair-permuted)

    const int tid  = threadIdx.x;
    const int lane = tid & 31;
    const int wid  = tid >> 5;
    const int gr   = lane >> 2;
    const int gc   = lane & 3;
    const int qt   = gridDim.x - 1 - blockIdx.x;   // long CTAs first
    const int bh   = blockIdx.y;
    const int arow = wid*16 + gr;

    // --- fill Q (pair-permuted over d)
    const float* Qg = g_q + ((size_t)bh * S_ + qt*128) * 64;
    for (int i = tid; i < 2048; i += 256) {
        int r = i >> 4, dc = (i & 15) << 2;
        float4 v = *(const float4*)(Qg + r*64 + dc);
        float* dst = &QP[r*FSTR + (dc & ~7) + ((dc & 4) ? 1 : 0)];
        dst[0] = v.x; dst[2] = v.y; dst[4] = v.z; dst[6] = v.w;
    }
    __syncthreads();

    // --- hoist Q fragments (loop-invariant)
    unsigned qa[8][4];
#pragma unroll
    for (int ks = 0; ks < 8; ks++) {
        uint2 lo = *(const uint2*)&QP[arow*FSTR + ks*8 + 2*gc];
        uint2 hi = *(const uint2*)&QP[(arow+8)*FSTR + ks*8 + 2*gc];
        qa[ks][0] = lo.x; qa[ks][1] = hi.x; qa[ks][2] = lo.y; qa[ks][3] = hi.y;
    }

    float o[8][4];
#pragma unroll
    for (int ni = 0; ni < 8; ni++)
#pragma unroll
        for (int j = 0; j < 4; j++) o[ni][j] = 0.f;
    float m0 = -INFINITY, m1 = -INFINITY, l0 = 0.f, l1 = 0.f;

    const int ktmax = 2*qt + 1;
    for (int kt = 0; kt <= ktmax; kt++) {
        __syncthreads();                 // prior P/V/K reads complete
        const float* Kg = g_k + ((size_t)bh * S_ + kt*64) * 64;
        const float* Vg = g_v + ((size_t)bh * S_ + kt*64) * 64;
        // K: pair-permuted rows (coalesced gmem load)
        for (int i = tid; i < 1024; i += 256) {
            int r = i >> 4, dc = (i & 15) << 2;
            float4 kv = *(const float4*)(Kg + r*64 + dc);
            float* kd = &Ks[r*FSTR + (dc & ~7) + ((dc & 4) ? 1 : 0)];
            kd[0] = kv.x; kd[2] = kv.y; kd[4] = kv.z; kd[6] = kv.w;
        }
        // V: transpose into Vt[d][pp(n)]; lanes span n -> STS conflict-free
        for (int i = tid; i < 1024; i += 256) {
            int r = i & 63;                      // n row in gmem
            int dc = (i >> 6) << 2;              // d col base
            float4 vv = *(const float4*)(Vg + r*64 + dc);
            int pc = (r & ~7) + 2*(r & 3) + ((r & 4) ? 1 : 0);
            Vt[(dc+0)*FSTR + pc] = vv.x;
            Vt[(dc+1)*FSTR + pc] = vv.y;
            Vt[(dc+2)*FSTR + pc] = vv.z;
            Vt[(dc+3)*FSTR + pc] = vv.w;
        }
        __syncthreads();

        // S = Q K^T  (already in log2 units)
        float sc[8][4];
#pragma unroll
        for (int ni = 0; ni < 8; ni++)
#pragma unroll
            for (int j = 0; j < 4; j++) sc[ni][j] = 0.f;
#pragma unroll
        for (int ks = 0; ks < 8; ks++) {
#pragma unroll
            for (int ni = 0; ni < 8; ni++) {
                uint2 bb = *(const uint2*)&Ks[(ni*8 + gr)*FSTR + ks*8 + 2*gc];
                unsigned b[2] = {bb.x, bb.y};
                mma_tf32(sc[ni], qa[ks], b);
            }
        }

        // causal mask (no scale needed — folded into Q)
        const int qrow0 = qt*128 + wid*16 + gr;
        const bool diag = (kt >= 2*qt);
        if (diag) {
#pragma unroll
            for (int ni = 0; ni < 8; ni++) {
                int col = kt*64 + ni*8 + 2*gc;
                if (col     > qrow0)     sc[ni][0] = -1e30f;
                if (col + 1 > qrow0)     sc[ni][1] = -1e30f;
                if (col     > qrow0 + 8) sc[ni][2] = -1e30f;
                if (col + 1 > qrow0 + 8) sc[ni][3] = -1e30f;
            }
        }

        // online softmax in log2 domain
        float mx0 = -INFINITY, mx1 = -INFINITY;
#pragma unroll
        for (int ni = 0; ni < 8; ni++) {
            mx0 = fmaxf(mx0, fmaxf(sc[ni][0], sc[ni][1]));
            mx1 = fmaxf(mx1, fmaxf(sc[ni][2], sc[ni][3]));
        }
        mx0 = fmaxf(mx0, __shfl_xor_sync(0xffffffffu, mx0, 1));
        mx0 = fmaxf(mx0, __shfl_xor_sync(0xffffffffu, mx0, 2));
        mx1 = fmaxf(mx1, __shfl_xor_sync(0xffffffffu, mx1, 1));
        mx1 = fmaxf(mx1, __shfl_xor_sync(0xffffffffu, mx1, 2));
        float mn0 = fmaxf(m0, mx0), mn1 = fmaxf(m1, mx1);
        float al0 = ex2(m0 - mn0), al1 = ex2(m1 - mn1);
        m0 = mn0; m1 = mn1;

        const int pp = (gc < 2) ? 4*gc : 4*gc - 7;
        float* pr0 = &QP[arow*FSTR];
        float* pr1 = &QP[(arow+8)*FSTR];
        float s0 = 0.f, s1 = 0.f;
#pragma unroll
        for (int ni = 0; ni < 8; ni++) {
            float p00 = ex2(sc[ni][0] - mn0);
            float p01 = ex2(sc[ni][1] - mn0);
            float p10 = ex2(sc[ni][2] - mn1);
            float p11 = ex2(sc[ni][3] - mn1);
            s0 += p00 + p01;
            s1 += p10 + p11;
            int c = ni*8 + pp;
            pr0[c]   = __uint_as_float(f2tf32(p00));
            pr0[c+2] = __uint_as_float(f2tf32(p01));
            pr1[c]   = __uint_as_float(f2tf32(p10));
            pr1[c+2] = __uint_as_float(f2tf32(p11));
        }
        s0 += __shfl_xor_sync(0xffffffffu, s0, 1);
        s0 += __shfl_xor_sync(0xffffffffu, s0, 2);
        s1 += __shfl_xor_sync(0xffffffffu, s1, 1);
        s1 += __shfl_xor_sync(0xffffffffu, s1, 2);
        l0 = l0 * al0 + s0;
        l1 = l1 * al1 + s1;

#pragma unroll
        for (int ni = 0; ni < 8; ni++) {
            o[ni][0] *= al0; o[ni][1] *= al0;
            o[ni][2] *= al1; o[ni][3] *= al1;
        }
        __syncwarp();                    // P rows are warp-private

        // O += P V   (b-frag: one LDS.64 from transposed pair-permuted Vt)
#pragma unroll
        for (int ks = 0; ks < 8; ks++) {
            uint2 plo = *(const uint2*)&QP[arow*FSTR + ks*8 + 2*gc];
            uint2 phi = *(const uint2*)&QP[(arow+8)*FSTR + ks*8 + 2*gc];
            unsigned pa[4] = {plo.x, phi.x, plo.y, phi.y};
#pragma unroll
            for (int ni = 0; ni < 8; ni++) {
                uint2 bb = *(const uint2*)&Vt[(ni*8 + gr)*FSTR + ks*8 + 2*gc];
                unsigned b[2] = {bb.x, bb.y};
                mma_tf32(o[ni], pa, b);
            }
        }
    }

    float inv0 = 1.f / l0, inv1 = 1.f / l1;
    const int b = bh / NH_, h = bh % NH_;
    const int srow0 = qt*128 + wid*16 + gr;
#pragma unroll
    for (int ni = 0; ni < 8; ni++) {
        int col = h*64 + ni*8 + 2*gc;
        *(float2*)(g_attn + (size_t)(b*S_ + srow0) * H_ + col) =
            make_float2(o[ni][0]*inv0, o[ni][1]*inv0);
        *(float2*)(g_attn + (size_t)(b*S_ + srow0 + 8) * H_ + col) =
            make_float2(o[ni][2]*inv1, o[ni][3]*inv1);
    }
}

// ---------------- launch --------------------------------------------------------------
extern "C" void kernel_launch(void* const* d_in, const int* in_sizes, int n_in,
                              void* d_out, int out_size) {
    (void)in_sizes; (void)n_in; (void)out_size;
    const float* x       = (const float*)d_in[0];
    const float* ve      = (const float*)d_in[1];
    const float* Wqkv    = (const float*)d_in[2];
    const float* Wo      = (const float*)d_in[3];
    const float* lambdas = (const float*)d_in[4];
    float* out = (float*)d_out;

    void *p_qkv, *p_attn;
    cudaGetSymbolAddress(&p_qkv,  g_qkv);
    cudaGetSymbolAddress(&p_attn, g_attn);

    static bool attr_done = false;
    if (!attr_done) {
        cudaFuncSetAttribute(flash_v3, cudaFuncAttributeMaxDynamicSharedMemorySize,
                             FLASH_SMEM_BYTES);
        cudaFuncSetAttribute(gemm_v2, cudaFuncAttributeMaxDynamicSharedMemorySize,
                             GEMM_SMEM_BYTES);
        attr_done = true;
    }

    // 1) qkv = x @ W_qkv^T
    gemm_v2<<<dim3(3*H_/128, ROWS_/128), 256, GEMM_SMEM_BYTES>>>(x, Wqkv, (float*)p_qkv,
                                                                 ROWS_, 3*H_, H_);
    // 2) RoPE table
    rope_table_kernel<<<(S_*32 + 255)/256, 256>>>();
    // 3) prep
    prep_kernel<<<(B_*S_*NH_*32 + 255)/256, 256>>>(ve, lambdas);
    // 4) causal flash attention
    flash_v3<<<dim3(S_/128, B_*NH_), 256, FLASH_SMEM_BYTES>>>();
    // 5) out = attn @ W_o^T
    gemm_v2<<<dim3(H_/128, ROWS_/128), 256, GEMM_SMEM_BYTES>>>((const float*)p_attn, Wo, out,
                                                               ROWS_, H_, H_);
}

// round 5
// speedup vs baseline: 1.0422x; 1.0422x over previous
#include <cuda_runtime.h>
#include <cuda_bf16.h>
#include <math.h>

// Problem constants
#define B_  2
#define S_  2048
#define H_  1024
#define NH_ 16
#define D_  64
#define ROWS_ (B_*S_)        // 4096
#define EPS_ 1.1920929e-07f
#define QSCALE_ (0.125f * 1.4426950408889634f)   // (1/sqrt(D)) * log2(e)

// ---------------- scratch -------------------------------------------------------------
__device__ float g_qkv[(size_t)ROWS_ * 3 * H_];
__device__ float g_q[(size_t)B_*NH_*S_*D_];
__device__ float g_k[(size_t)B_*NH_*S_*D_];
__device__ float g_v[(size_t)B_*NH_*S_*D_];
__device__ float g_attn[(size_t)ROWS_ * H_];
__device__ float g_cos[S_*32];
__device__ float g_sin[S_*32];

// ---------------- helpers -------------------------------------------------------------
__device__ __forceinline__ unsigned f2tf32(float f) {
    unsigned u;
    asm("cvt.rna.tf32.f32 %0, %1;" : "=r"(u) : "f"(f));
    return u;
}
__device__ __forceinline__ float ex2(float x) {
    float r;
    asm("ex2.approx.f32 %0, %1;" : "=f"(r) : "f"(x));
    return r;
}
__device__ __forceinline__ void mma_tf32(float c[4], const unsigned a[4], const unsigned b[2]) {
    asm volatile(
        "mma.sync.aligned.m16n8k8.row.col.f32.tf32.tf32.f32 "
        "{%0,%1,%2,%3}, {%4,%5,%6,%7}, {%8,%9}, {%0,%1,%2,%3};"
        : "+f"(c[0]), "+f"(c[1]), "+f"(c[2]), "+f"(c[3])
        : "r"(a[0]), "r"(a[1]), "r"(a[2]), "r"(a[3]), "r"(b[0]), "r"(b[1]));
}
__device__ __forceinline__ void cp16(unsigned dst, const void* src) {
    asm volatile("cp.async.cg.shared.global [%0], [%1], 16;" :: "r"(dst), "l"(src));
}

// ---------------- RoPE table ----------------------------------------------------------
__global__ void rope_table_kernel() {
    int idx = blockIdx.x * blockDim.x + threadIdx.x;
    if (idx >= S_*32) return;
    int s = idx >> 5, j = idx & 31;
    double invf = pow(1.0e-4, (double)j / 32.0);
    float f = (float)s * (float)invf;
    double sn, cs;
    sincos((double)f, &sn, &cs);
    g_cos[idx] = (float)cs;
    g_sin[idx] = (float)sn;
}

// ---------------- tf32 GEMM: C[M,N] = A[M,K] * B[N,K]^T (unchanged from R4) -----------
#define GSTR 40
#define GEMM_SMEM_BYTES (4*128*GSTR*4)   // 80KB

__global__ __launch_bounds__(256, 2)
void gemm_v2(const float* __restrict__ A, const float* __restrict__ Bm,
             float* __restrict__ C, int M, int N, int K) {
    extern __shared__ unsigned smg[];
    unsigned* As = smg;
    unsigned* Bs = smg + 2*128*GSTR;

    const int tid  = threadIdx.x;
    const int lane = tid & 31;
    const int wid  = tid >> 5;
    const int gr   = lane >> 2;
    const int gc   = lane & 3;
    const int bm = blockIdx.y * 128;
    const int bn = blockIdx.x * 128;
    const int wm = (wid >> 1) * 32;
    const int wn = (wid & 1) * 64;

    const int lrow = tid >> 1;
    const int lg   = tid & 1;
    const float* Ag = A  + (size_t)(bm + lrow) * K + lg*8;
    const float* Bg = Bm + (size_t)(bn + lrow) * K + lg*8;

    float4 ra0, ra1, rb0, rb1;
    float acc[2][8][4];
#pragma unroll
    for (int mi = 0; mi < 2; mi++)
#pragma unroll
        for (int ni = 0; ni < 8; ni++)
#pragma unroll
            for (int j = 0; j < 4; j++) acc[mi][ni][j] = 0.f;

    ra0 = *(const float4*)(Ag);  ra1 = *(const float4*)(Ag + 4);
    rb0 = *(const float4*)(Bg);  rb1 = *(const float4*)(Bg + 4);
    {
        unsigned* da = &As[lrow*GSTR + lg*8];
        da[0]=f2tf32(ra0.x); da[2]=f2tf32(ra0.y); da[4]=f2tf32(ra0.z); da[6]=f2tf32(ra0.w);
        da[1]=f2tf32(ra1.x); da[3]=f2tf32(ra1.y); da[5]=f2tf32(ra1.z); da[7]=f2tf32(ra1.w);
        unsigned* db = &Bs[lrow*GSTR + lg*8];
        db[0]=f2tf32(rb0.x); db[2]=f2tf32(rb0.y); db[4]=f2tf32(rb0.z); db[6]=f2tf32(rb0.w);
        db[1]=f2tf32(rb1.x); db[3]=f2tf32(rb1.y); db[5]=f2tf32(rb1.z); db[7]=f2tf32(rb1.w);
    }
    __syncthreads();

    const int T = K >> 4;
    for (int t = 0; t < T; t++) {
        const int cur = t & 1;
        if (t + 1 < T) {
            int k0 = (t+1) << 4;
            ra0 = *(const float4*)(Ag + k0);  ra1 = *(const float4*)(Ag + k0 + 4);
            rb0 = *(const float4*)(Bg + k0);  rb1 = *(const float4*)(Bg + k0 + 4);
        }
        const unsigned* Ab = &As[cur*128*GSTR];
        const unsigned* Bb = &Bs[cur*128*GSTR];
#pragma unroll
        for (int ks = 0; ks < 2; ks++) {
            unsigned a[2][4];
#pragma unroll
            for (int mi = 0; mi < 2; mi++) {
                uint2 lo = *(const uint2*)&Ab[(wm + mi*16 + gr)*GSTR + ks*8 + 2*gc];
                uint2 hi = *(const uint2*)&Ab[(wm + mi*16 + 8 + gr)*GSTR + ks*8 + 2*gc];
                a[mi][0] = lo.x; a[mi][1] = hi.x; a[mi][2] = lo.y; a[mi][3] = hi.y;
            }
#pragma unroll
            for (int ni = 0; ni < 8; ni++) {
                uint2 bb = *(const uint2*)&Bb[(wn + ni*8 + gr)*GSTR + ks*8 + 2*gc];
                unsigned b[2] = {bb.x, bb.y};
                mma_tf32(acc[0][ni], a[0], b);
                mma_tf32(acc[1][ni], a[1], b);
            }
        }
        if (t + 1 < T) {
            int nst = (t+1) & 1;
            unsigned* da = &As[nst*128*GSTR + lrow*GSTR + lg*8];
            da[0]=f2tf32(ra0.x); da[2]=f2tf32(ra0.y); da[4]=f2tf32(ra0.z); da[6]=f2tf32(ra0.w);
            da[1]=f2tf32(ra1.x); da[3]=f2tf32(ra1.y); da[5]=f2tf32(ra1.z); da[7]=f2tf32(ra1.w);
            unsigned* db = &Bs[nst*128*GSTR + lrow*GSTR + lg*8];
            db[0]=f2tf32(rb0.x); db[2]=f2tf32(rb0.y); db[4]=f2tf32(rb0.z); db[6]=f2tf32(rb0.w);
            db[1]=f2tf32(rb1.x); db[3]=f2tf32(rb1.y); db[5]=f2tf32(rb1.z); db[7]=f2tf32(rb1.w);
        }
        __syncthreads();
    }

#pragma unroll
    for (int mi = 0; mi < 2; mi++) {
        int m0 = bm + wm + mi*16 + gr;
#pragma unroll
        for (int ni = 0; ni < 8; ni++) {
            int n = bn + wn + ni*8 + 2*gc;
            *(float2*)(C + (size_t)m0 * N + n)       = make_float2(acc[mi][ni][0], acc[mi][ni][1]);
            *(float2*)(C + (size_t)(m0 + 8) * N + n) = make_float2(acc[mi][ni][2], acc[mi][ni][3]);
        }
    }
}

// ---------------- prep (unchanged from R4) --------------------------------------------
__global__ void prep_kernel(const float* __restrict__ ve, const float* __restrict__ lambdas) {
    int gtid = blockIdx.x * blockDim.x + threadIdx.x;
    int warp = gtid >> 5;
    int lane = gtid & 31;
    if (warp >= B_*S_*NH_) return;
    int h = warp % NH_;
    int s = (warp / NH_) % S_;
    int b = warp / (NH_ * S_);

    const float* row = g_qkv + (size_t)(b*S_ + s) * (3*H_);
    float q1 = row[h*64 + lane],          q2 = row[h*64 + 32 + lane];
    float k1 = row[H_ + h*64 + lane],     k2 = row[H_ + h*64 + 32 + lane];
    float v1 = row[2*H_ + h*64 + lane],   v2 = row[2*H_ + h*64 + 32 + lane];

    float sq = q1*q1 + q2*q2;
    float sk = k1*k1 + k2*k2;
#pragma unroll
    for (int o = 16; o; o >>= 1) {
        sq += __shfl_xor_sync(0xffffffffu, sq, o);
        sk += __shfl_xor_sync(0xffffffffu, sk, o);
    }
    float rq = rsqrtf(sq * (1.f/64.f) + EPS_);
    float rk = rsqrtf(sk * (1.f/64.f) + EPS_);
    q1 *= rq; q2 *= rq; k1 *= rk; k2 *= rk;

    float c  = g_cos[s*32 + lane];
    float sn = g_sin[s*32 + lane];
    float qo1 = (q1*c + q2*sn) * QSCALE_;
    float qo2 = (q2*c - q1*sn) * QSCALE_;
    float ko1 = k1*c + k2*sn, ko2 = k2*c - k1*sn;

    float l0 = lambdas[0], l1 = lambdas[1];
    const float* verow = ve + (size_t)(b*S_ + s) * H_ + h*64;
    float vo1 = l0*v1 + l1*verow[lane];
    float vo2 = l0*v2 + l1*verow[32 + lane];

    size_t o = ((size_t)(b*NH_ + h) * S_ + s) * 64 + lane;
    g_q[o]    = __uint_as_float(f2tf32(qo1));
    g_q[o+32] = __uint_as_float(f2tf32(qo2));
    g_k[o]    = __uint_as_float(f2tf32(ko1));
    g_k[o+32] = __uint_as_float(f2tf32(ko2));
    g_v[o]    = __uint_as_float(f2tf32(vo1));
    g_v[o+32] = __uint_as_float(f2tf32(vo2));
}

// ---------------- flash attention v4: cp.async double-buffered K/V --------------------
// BM=128, BN=64, 256 thr = 8 warps; warp w owns q rows [16w,16w+16).
// Layouts (R2-proven, stride 68, natural): QP[128][68] (Q then P), Ks[2][64][68],
// Vs[2][64][68]. Q frags hoisted to regs. K/V tile kt+1 prefetched via cp.async.cg
// while tile kt computes. smem = 104,448B -> 2 CTAs/SM with launch_bounds(256,2).
#define FSTR 68
#define STAGE_W (64*FSTR)                     // words per stage
#define FLASH_SMEM_BYTES ((128*FSTR + 4*STAGE_W)*4)   // 104448

__global__ __launch_bounds__(256, 2)
void flash_v4() {
    extern __shared__ float sm[];
    float* QP = sm;                           // 128 x 68 (Q, then P[m][n])
    float* Ks = sm + 128*FSTR;                // 2 x 64 x 68
    float* Vs = Ks + 2*STAGE_W;               // 2 x 64 x 68

    const int tid  = threadIdx.x;
    const int lane = tid & 31;
    const int wid  = tid >> 5;
    const int gr   = lane >> 2;
    const int gc   = lane & 3;
    const int qt   = gridDim.x - 1 - blockIdx.x;   // long CTAs first
    const int bh   = blockIdx.y;
    const int arow = wid*16 + gr;

    const unsigned ks_u32 = (unsigned)__cvta_generic_to_shared(Ks);
    const unsigned vs_u32 = (unsigned)__cvta_generic_to_shared(Vs);
    const float* Kbase = g_k + (size_t)bh * S_ * 64;
    const float* Vbase = g_v + (size_t)bh * S_ * 64;
    const int ktmax = 2*qt + 1;

    // row/col this thread copies (4 chunks per matrix per stage fill)
    const int cr = tid >> 4;                  // 0..15 (row step 16)
    const int cc = (tid & 15) << 2;           // 0,4,...,60

    // ---- prologue: async-load stage 0 (kt=0)
    {
        const float* Kg = Kbase;  const float* Vg = Vbase;
#pragma unroll
        for (int j = 0; j < 4; j++) {
            int r = cr + j*16;
            unsigned off = (unsigned)((r*FSTR + cc) * 4);
            cp16(ks_u32 + off, Kg + r*64 + cc);
            cp16(vs_u32 + off, Vg + r*64 + cc);
        }
        asm volatile("cp.async.commit_group;");
    }

    // ---- fill Q (natural [m][d])
    const float* Qg = g_q + ((size_t)bh * S_ + qt*128) * 64;
    for (int i = tid; i < 2048; i += 256) {
        int r = i >> 4, dc = (i & 15) << 2;
        *(float4*)&QP[r*FSTR + dc] = *(const float4*)(Qg + r*64 + dc);
    }
    __syncthreads();

    // ---- hoist Q fragments
    unsigned qa[8][4];
#pragma unroll
    for (int ks = 0; ks < 8; ks++) {
        const float* ap = &QP[arow*FSTR + ks*8 + gc];
        qa[ks][0] = __float_as_uint(ap[0]);
        qa[ks][1] = __float_as_uint(ap[8*FSTR]);
        qa[ks][2] = __float_as_uint(ap[4]);
        qa[ks][3] = __float_as_uint(ap[8*FSTR + 4]);
    }

    float o[8][4];
#pragma unroll
    for (int ni = 0; ni < 8; ni++)
#pragma unroll
        for (int j = 0; j < 4; j++) o[ni][j] = 0.f;
    float m0 = -INFINITY, m1 = -INFINITY, l0 = 0.f, l1 = 0.f;

    for (int kt = 0; kt <= ktmax; kt++) {
        const int cur = kt & 1;
        __syncthreads();                      // all reads of stage cur^1 (and Q hoist) done

        if (kt < ktmax) {                     // prefetch kt+1 into spare stage
            const int nst = cur ^ 1;
            const float* Kg = Kbase + (size_t)(kt+1)*64*64;
            const float* Vg = Vbase + (size_t)(kt+1)*64*64;
            unsigned kd = ks_u32 + (unsigned)(nst*STAGE_W*4);
            unsigned vd = vs_u32 + (unsigned)(nst*STAGE_W*4);
#pragma unroll
            for (int j = 0; j < 4; j++) {
                int r = cr + j*16;
                unsigned off = (unsigned)((r*FSTR + cc) * 4);
                cp16(kd + off, Kg + r*64 + cc);
                cp16(vd + off, Vg + r*64 + cc);
            }
            asm volatile("cp.async.commit_group;");
            asm volatile("cp.async.wait_group 1;");   // stage cur complete
        } else {
            asm volatile("cp.async.wait_group 0;");
        }
        __syncthreads();                      // publish stage cur to all warps

        const float* Kst = Ks + cur*STAGE_W;
        const float* Vst = Vs + cur*STAGE_W;

        // S = Q K^T  (log2 units; scale folded into Q)
        float sc[8][4];
#pragma unroll
        for (int ni = 0; ni < 8; ni++)
#pragma unroll
            for (int j = 0; j < 4; j++) sc[ni][j] = 0.f;
#pragma unroll
        for (int ks = 0; ks < 8; ks++) {
#pragma unroll
            for (int ni = 0; ni < 8; ni++) {
                const float* bp = Kst + (ni*8 + gr)*FSTR + ks*8 + gc;
                unsigned b[2] = { __float_as_uint(bp[0]), __float_as_uint(bp[4]) };
                mma_tf32(sc[ni], qa[ks], b);
            }
        }

        // causal mask
        const int qrow0 = qt*128 + wid*16 + gr;
        if (kt >= 2*qt) {
#pragma unroll
            for (int ni = 0; ni < 8; ni++) {
                int col = kt*64 + ni*8 + 2*gc;
                if (col     > qrow0)     sc[ni][0] = -1e30f;
                if (col + 1 > qrow0)     sc[ni][1] = -1e30f;
                if (col     > qrow0 + 8) sc[ni][2] = -1e30f;
                if (col + 1 > qrow0 + 8) sc[ni][3] = -1e30f;
            }
        }

        // online softmax (log2 domain, rows in 4-lane quads)
        float mx0 = -INFINITY, mx1 = -INFINITY;
#pragma unroll
        for (int ni = 0; ni < 8; ni++) {
            mx0 = fmaxf(mx0, fmaxf(sc[ni][0], sc[ni][1]));
            mx1 = fmaxf(mx1, fmaxf(sc[ni][2], sc[ni][3]));
        }
        mx0 = fmaxf(mx0, __shfl_xor_sync(0xffffffffu, mx0, 1));
        mx0 = fmaxf(mx0, __shfl_xor_sync(0xffffffffu, mx0, 2));
        mx1 = fmaxf(mx1, __shfl_xor_sync(0xffffffffu, mx1, 1));
        mx1 = fmaxf(mx1, __shfl_xor_sync(0xffffffffu, mx1, 2));
        float mn0 = fmaxf(m0, mx0), mn1 = fmaxf(m1, mx1);
        float al0 = ex2(m0 - mn0), al1 = ex2(m1 - mn1);
        m0 = mn0; m1 = mn1;

        float* pr0 = &QP[arow*FSTR];
        float* pr1 = &QP[(arow+8)*FSTR];
        float s0 = 0.f, s1 = 0.f;
#pragma unroll
        for (int ni = 0; ni < 8; ni++) {
            float p00 = ex2(sc[ni][0] - mn0);
            float p01 = ex2(sc[ni][1] - mn0);
            float p10 = ex2(sc[ni][2] - mn1);
            float p11 = ex2(sc[ni][3] - mn1);
            s0 += p00 + p01;
            s1 += p10 + p11;
            int c = ni*8 + 2*gc;
            *(float2*)&pr0[c] = make_float2(__uint_as_float(f2tf32(p00)),
                                            __uint_as_float(f2tf32(p01)));
            *(float2*)&pr1[c] = make_float2(__uint_as_float(f2tf32(p10)),
                                            __uint_as_float(f2tf32(p11)));
        }
        s0 += __shfl_xor_sync(0xffffffffu, s0, 1);
        s0 += __shfl_xor_sync(0xffffffffu, s0, 2);
        s1 += __shfl_xor_sync(0xffffffffu, s1, 1);
        s1 += __shfl_xor_sync(0xffffffffu, s1, 2);
        l0 = l0 * al0 + s0;
        l1 = l1 * al1 + s1;

#pragma unroll
        for (int ni = 0; ni < 8; ni++) {
            o[ni][0] *= al0; o[ni][1] *= al0;
            o[ni][2] *= al1; o[ni][3] *= al1;
        }
        __syncwarp();                         // P rows warp-private

        // O += P V
#pragma unroll
        for (int ks = 0; ks < 8; ks++) {
            const float* ap = &QP[arow*FSTR + ks*8 + gc];
            unsigned pa[4] = { __float_as_uint(ap[0]),  __float_as_uint(ap[8*FSTR]),
                               __float_as_uint(ap[4]),  __float_as_uint(ap[8*FSTR + 4]) };
#pragma unroll
            for (int ni = 0; ni < 8; ni++) {
                unsigned b[2] = { __float_as_uint(Vst[(ks*8 + gc)*FSTR + ni*8 + gr]),
                                  __float_as_uint(Vst[(ks*8 + gc + 4)*FSTR + ni*8 + gr]) };
                mma_tf32(o[ni], pa, b);
            }
        }
    }

    float inv0 = 1.f / l0, inv1 = 1.f / l1;
    const int b = bh / NH_, h = bh % NH_;
    const int srow0 = qt*128 + wid*16 + gr;
#pragma unroll
    for (int ni = 0; ni < 8; ni++) {
        int col = h*64 + ni*8 + 2*gc;
        *(float2*)(g_attn + (size_t)(b*S_ + srow0) * H_ + col) =
            make_float2(o[ni][0]*inv0, o[ni][1]*inv0);
        *(float2*)(g_attn + (size_t)(b*S_ + srow0 + 8) * H_ + col) =
            make_float2(o[ni][2]*inv1, o[ni][3]*inv1);
    }
}

// ---------------- launch --------------------------------------------------------------
extern "C" void kernel_launch(void* const* d_in, const int* in_sizes, int n_in,
                              void* d_out, int out_size) {
    (void)in_sizes; (void)n_in; (void)out_size;
    const float* x       = (const float*)d_in[0];
    const float* ve      = (const float*)d_in[1];
    const float* Wqkv    = (const float*)d_in[2];
    const float* Wo      = (const float*)d_in[3];
    const float* lambdas = (const float*)d_in[4];
    float* out = (float*)d_out;

    void *p_qkv, *p_attn;
    cudaGetSymbolAddress(&p_qkv,  g_qkv);
    cudaGetSymbolAddress(&p_attn, g_attn);

    static bool attr_done = false;
    if (!attr_done) {
        cudaFuncSetAttribute(flash_v4, cudaFuncAttributeMaxDynamicSharedMemorySize,
                             FLASH_SMEM_BYTES);
        cudaFuncSetAttribute(gemm_v2, cudaFuncAttributeMaxDynamicSharedMemorySize,
                             GEMM_SMEM_BYTES);
        attr_done = true;
    }

    // 1) qkv = x @ W_qkv^T
    gemm_v2<<<dim3(3*H_/128, ROWS_/128), 256, GEMM_SMEM_BYTES>>>(x, Wqkv, (float*)p_qkv,
                                                                 ROWS_, 3*H_, H_);
    // 2) RoPE table
    rope_table_kernel<<<(S_*32 + 255)/256, 256>>>();
    // 3) prep
    prep_kernel<<<(B_*S_*NH_*32 + 255)/256, 256>>>(ve, lambdas);
    // 4) causal flash attention (cp.async pipelined)
    flash_v4<<<dim3(S_/128, B_*NH_), 256, FLASH_SMEM_BYTES>>>();
    // 5) out = attn @ W_o^T
    gemm_v2<<<dim3(H_/128, ROWS_/128), 256, GEMM_SMEM_BYTES>>>((const float*)p_attn, Wo, out,
                                                               ROWS_, H_, H_);
}

// round 7
// speedup vs baseline: 1.0940x; 1.0497x over previous
#include <cuda_runtime.h>
#include <cuda_bf16.h>
#include <math.h>
#include <stdint.h>

// Problem constants
#define B_  2
#define S_  2048
#define H_  1024
#define NH_ 16
#define D_  64
#define ROWS_ (B_*S_)        // 4096
#define EPS_ 1.1920929e-07f
#define QSCALE_ (0.125f * 1.4426950408889634f)   // (1/sqrt(D)) * log2(e)

// ---------------- scratch -------------------------------------------------------------
__device__ float g_qkv[(size_t)ROWS_ * 3 * H_];
__device__ float g_q[(size_t)B_*NH_*S_*D_];
__device__ float g_k[(size_t)B_*NH_*S_*D_];
__device__ float g_v[(size_t)B_*NH_*S_*D_];
__device__ float g_attn[(size_t)ROWS_ * H_];
__device__ float g_cos[S_*32];
__device__ float g_sin[S_*32];

// ---------------- helpers -------------------------------------------------------------
__device__ __forceinline__ unsigned f2tf32(float f) {
    unsigned u;
    asm("cvt.rna.tf32.f32 %0, %1;" : "=r"(u) : "f"(f));
    return u;
}
__device__ __forceinline__ float ex2(float x) {
    float r;
    asm("ex2.approx.f32 %0, %1;" : "=f"(r) : "f"(x));
    return r;
}
__device__ __forceinline__ void mma_tf32(float c[4], const unsigned a[4], const unsigned b[2]) {
    asm volatile(
        "mma.sync.aligned.m16n8k8.row.col.f32.tf32.tf32.f32 "
        "{%0,%1,%2,%3}, {%4,%5,%6,%7}, {%8,%9}, {%0,%1,%2,%3};"
        : "+f"(c[0]), "+f"(c[1]), "+f"(c[2]), "+f"(c[3])
        : "r"(a[0]), "r"(a[1]), "r"(a[2]), "r"(a[3]), "r"(b[0]), "r"(b[1]));
}
__device__ __forceinline__ void cp16(unsigned dst, const void* src) {
    asm volatile("cp.async.cg.shared.global [%0], [%1], 16;" :: "r"(dst), "l"(src));
}
__device__ __forceinline__ uint32_t smem_u32(const void* p) {
    return (uint32_t)__cvta_generic_to_shared(p);
}

// ---------------- RoPE table ----------------------------------------------------------
__global__ void rope_table_kernel() {
    int idx = blockIdx.x * blockDim.x + threadIdx.x;
    if (idx >= S_*32) return;
    int s = idx >> 5, j = idx & 31;
    double invf = pow(1.0e-4, (double)j / 32.0);
    float f = (float)s * (float)invf;
    double sn, cs;
    sincos((double)f, &sn, &cs);
    g_cos[idx] = (float)cs;
    g_sin[idx] = (float)sn;
}

// ---------------- tf32 GEMM v3: C[M,N] = A[M,K] * B[N,K]^T ----------------------------
// R2-proven layout (As[128][20] [m][k], scalar frag LDS, STS.128 stores) + the ONE
// structural change: 2 smem stages + register-staged gmem prefetch, 1 sync per slab.
// 128x128 tile, BK=16, 256 thr = 8 warps (4m x 2n), warp tile 32x64.
// smem: 2 stages x (A 10KB + B 10KB) = 40KB -> 2 CTAs/SM (launch_bounds pins regs).
#define GPAD 20
#define GSTG (128*GPAD)                        // words per matrix per stage
#define GEMM_SMEM_BYTES (4*GSTG*4)             // 40960

__global__ __launch_bounds__(256, 2)
void gemm_v3(const float* __restrict__ A, const float* __restrict__ Bm,
             float* __restrict__ C, int M, int N, int K) {
    extern __shared__ unsigned smg[];
    unsigned* As = smg;                        // [2][128][GPAD]
    unsigned* Bs = smg + 2*GSTG;

    const int tid  = threadIdx.x;
    const int lane = tid & 31;
    const int wid  = tid >> 5;
    const int gr   = lane >> 2;
    const int gc   = lane & 3;
    const int bm = blockIdx.y * 128;
    const int bn = blockIdx.x * 128;
    const int wm = (wid >> 1) * 32;
    const int wn = (wid & 1) * 64;

    const int lr = tid >> 2;                   // 0..63 loader row
    const int lc = (tid & 3) << 2;             // 0,4,8,12

    const float* Ag0 = A  + (size_t)(bm + lr) * K + lc;
    const float* Ag1 = A  + (size_t)(bm + lr + 64) * K + lc;
    const float* Bg0 = Bm + (size_t)(bn + lr) * K + lc;
    const float* Bg1 = Bm + (size_t)(bn + lr + 64) * K + lc;

    float acc[2][8][4];
#pragma unroll
    for (int mi = 0; mi < 2; mi++)
#pragma unroll
        for (int ni = 0; ni < 8; ni++)
#pragma unroll
            for (int j = 0; j < 4; j++) acc[mi][ni][j] = 0.f;

    float4 ra0, ra1, rb0, rb1;

    // prologue: slab 0 -> stage 0
    ra0 = *(const float4*)(Ag0); ra1 = *(const float4*)(Ag1);
    rb0 = *(const float4*)(Bg0); rb1 = *(const float4*)(Bg1);
    *(uint4*)&As[lr*GPAD + lc] =
        make_uint4(f2tf32(ra0.x), f2tf32(ra0.y), f2tf32(ra0.z), f2tf32(ra0.w));
    *(uint4*)&As[(lr+64)*GPAD + lc] =
        make_uint4(f2tf32(ra1.x), f2tf32(ra1.y), f2tf32(ra1.z), f2tf32(ra1.w));
    *(uint4*)&Bs[lr*GPAD + lc] =
        make_uint4(f2tf32(rb0.x), f2tf32(rb0.y), f2tf32(rb0.z), f2tf32(rb0.w));
    *(uint4*)&Bs[(lr+64)*GPAD + lc] =
        make_uint4(f2tf32(rb1.x), f2tf32(rb1.y), f2tf32(rb1.z), f2tf32(rb1.w));
    __syncthreads();

    const int T = K >> 4;
    for (int t = 0; t < T; t++) {
        const int cur = t & 1;
        if (t + 1 < T) {                       // prefetch slab t+1 into registers
            int k0 = (t + 1) << 4;
            ra0 = *(const float4*)(Ag0 + k0);  ra1 = *(const float4*)(Ag1 + k0);
            rb0 = *(const float4*)(Bg0 + k0);  rb1 = *(const float4*)(Bg1 + k0);
        }

        const unsigned* Ab = As + cur*GSTG;
        const unsigned* Bb = Bs + cur*GSTG;
#pragma unroll
        for (int ks = 0; ks < 2; ks++) {
            const int kb = ks * 8;
            unsigned a[2][4];
#pragma unroll
            for (int mi = 0; mi < 2; mi++) {
                const unsigned* ap = &Ab[(wm + mi*16 + gr)*GPAD + kb + gc];
                a[mi][0] = ap[0];
                a[mi][1] = ap[8*GPAD];
                a[mi][2] = ap[4];
                a[mi][3] = ap[8*GPAD + 4];
            }
#pragma unroll
            for (int ni = 0; ni < 8; ni++) {
                const unsigned* bp = &Bb[(wn + ni*8 + gr)*GPAD + kb + gc];
                unsigned b[2] = { bp[0], bp[4] };
                mma_tf32(acc[0][ni], a[0], b);
                mma_tf32(acc[1][ni], a[1], b);
            }
        }

        if (t + 1 < T) {                       // store prefetched slab -> spare stage
            unsigned* Ad = As + (cur^1)*GSTG;
            unsigned* Bd = Bs + (cur^1)*GSTG;
            *(uint4*)&Ad[lr*GPAD + lc] =
                make_uint4(f2tf32(ra0.x), f2tf32(ra0.y), f2tf32(ra0.z), f2tf32(ra0.w));
            *(uint4*)&Ad[(lr+64)*GPAD + lc] =
                make_uint4(f2tf32(ra1.x), f2tf32(ra1.y), f2tf32(ra1.z), f2tf32(ra1.w));
            *(uint4*)&Bd[lr*GPAD + lc] =
                make_uint4(f2tf32(rb0.x), f2tf32(rb0.y), f2tf32(rb0.z), f2tf32(rb0.w));
            *(uint4*)&Bd[(lr+64)*GPAD + lc] =
                make_uint4(f2tf32(rb1.x), f2tf32(rb1.y), f2tf32(rb1.z), f2tf32(rb1.w));
        }
        __syncthreads();
    }

#pragma unroll
    for (int mi = 0; mi < 2; mi++) {
        int m0 = bm + wm + mi*16 + gr;
#pragma unroll
        for (int ni = 0; ni < 8; ni++) {
            int n = bn + wn + ni*8 + 2*gc;
            *(float2*)(C + (size_t)m0 * N + n)       = make_float2(acc[mi][ni][0], acc[mi][ni][1]);
            *(float2*)(C + (size_t)(m0 + 8) * N + n) = make_float2(acc[mi][ni][2], acc[mi][ni][3]);
        }
    }
}

// ---------------- prep (unchanged) ----------------------------------------------------
__global__ void prep_kernel(const float* __restrict__ ve, const float* __restrict__ lambdas) {
    int gtid = blockIdx.x * blockDim.x + threadIdx.x;
    int warp = gtid >> 5;
    int lane = gtid & 31;
    if (warp >= B_*S_*NH_) return;
    int h = warp % NH_;
    int s = (warp / NH_) % S_;
    int b = warp / (NH_ * S_);

    const float* row = g_qkv + (size_t)(b*S_ + s) * (3*H_);
    float q1 = row[h*64 + lane],          q2 = row[h*64 + 32 + lane];
    float k1 = row[H_ + h*64 + lane],     k2 = row[H_ + h*64 + 32 + lane];
    float v1 = row[2*H_ + h*64 + lane],   v2 = row[2*H_ + h*64 + 32 + lane];

    float sq = q1*q1 + q2*q2;
    float sk = k1*k1 + k2*k2;
#pragma unroll
    for (int o = 16; o; o >>= 1) {
        sq += __shfl_xor_sync(0xffffffffu, sq, o);
        sk += __shfl_xor_sync(0xffffffffu, sk, o);
    }
    float rq = rsqrtf(sq * (1.f/64.f) + EPS_);
    float rk = rsqrtf(sk * (1.f/64.f) + EPS_);
    q1 *= rq; q2 *= rq; k1 *= rk; k2 *= rk;

    float c  = g_cos[s*32 + lane];
    float sn = g_sin[s*32 + lane];
    float qo1 = (q1*c + q2*sn) * QSCALE_;
    float qo2 = (q2*c - q1*sn) * QSCALE_;
    float ko1 = k1*c + k2*sn, ko2 = k2*c - k1*sn;

    float l0 = lambdas[0], l1 = lambdas[1];
    const float* verow = ve + (size_t)(b*S_ + s) * H_ + h*64;
    float vo1 = l0*v1 + l1*verow[lane];
    float vo2 = l0*v2 + l1*verow[32 + lane];

    size_t o = ((size_t)(b*NH_ + h) * S_ + s) * 64 + lane;
    g_q[o]    = __uint_as_float(f2tf32(qo1));
    g_q[o+32] = __uint_as_float(f2tf32(qo2));
    g_k[o]    = __uint_as_float(f2tf32(ko1));
    g_k[o+32] = __uint_as_float(f2tf32(ko2));
    g_v[o]    = __uint_as_float(f2tf32(vo1));
    g_v[o+32] = __uint_as_float(f2tf32(vo2));
}

// ---------------- flash attention v4 (unchanged from R5 — best flash) -----------------
#define FSTR 68
#define STAGE_W (64*FSTR)
#define FLASH_SMEM_BYTES ((128*FSTR + 4*STAGE_W)*4)   // 104448

__global__ __launch_bounds__(256, 2)
void flash_v4() {
    extern __shared__ float sm[];
    float* QP = sm;
    float* Ks = sm + 128*FSTR;
    float* Vs = Ks + 2*STAGE_W;

    const int tid  = threadIdx.x;
    const int lane = tid & 31;
    const int wid  = tid >> 5;
    const int gr   = lane >> 2;
    const int gc   = lane & 3;
    const int qt   = gridDim.x - 1 - blockIdx.x;
    const int bh   = blockIdx.y;
    const int arow = wid*16 + gr;

    const unsigned ks_u32 = smem_u32(Ks);
    const unsigned vs_u32 = smem_u32(Vs);
    const float* Kbase = g_k + (size_t)bh * S_ * 64;
    const float* Vbase = g_v + (size_t)bh * S_ * 64;
    const int ktmax = 2*qt + 1;

    const int cr = tid >> 4;
    const int cc = (tid & 15) << 2;

    {
        const float* Kg = Kbase;  const float* Vg = Vbase;
#pragma unroll
        for (int j = 0; j < 4; j++) {
            int r = cr + j*16;
            unsigned off = (unsigned)((r*FSTR + cc) * 4);
            cp16(ks_u32 + off, Kg + r*64 + cc);
            cp16(vs_u32 + off, Vg + r*64 + cc);
        }
        asm volatile("cp.async.commit_group;");
    }

    const float* Qg = g_q + ((size_t)bh * S_ + qt*128) * 64;
    for (int i = tid; i < 2048; i += 256) {
        int r = i >> 4, dc = (i & 15) << 2;
        *(float4*)&QP[r*FSTR + dc] = *(const float4*)(Qg + r*64 + dc);
    }
    __syncthreads();

    unsigned qa[8][4];
#pragma unroll
    for (int ks = 0; ks < 8; ks++) {
        const float* ap = &QP[arow*FSTR + ks*8 + gc];
        qa[ks][0] = __float_as_uint(ap[0]);
        qa[ks][1] = __float_as_uint(ap[8*FSTR]);
        qa[ks][2] = __float_as_uint(ap[4]);
        qa[ks][3] = __float_as_uint(ap[8*FSTR + 4]);
    }

    float o[8][4];
#pragma unroll
    for (int ni = 0; ni < 8; ni++)
#pragma unroll
        for (int j = 0; j < 4; j++) o[ni][j] = 0.f;
    float m0 = -INFINITY, m1 = -INFINITY, l0 = 0.f, l1 = 0.f;

    for (int kt = 0; kt <= ktmax; kt++) {
        const int cur = kt & 1;
        __syncthreads();

        if (kt < ktmax) {
            const int nst = cur ^ 1;
            const float* Kg = Kbase + (size_t)(kt+1)*64*64;
            const float* Vg = Vbase + (size_t)(kt+1)*64*64;
            unsigned kd = ks_u32 + (unsigned)(nst*STAGE_W*4);
            unsigned vd = vs_u32 + (unsigned)(nst*STAGE_W*4);
#pragma unroll
            for (int j = 0; j < 4; j++) {
                int r = cr + j*16;
                unsigned off = (unsigned)((r*FSTR + cc) * 4);
                cp16(kd + off, Kg + r*64 + cc);
                cp16(vd + off, Vg + r*64 + cc);
            }
            asm volatile("cp.async.commit_group;");
            asm volatile("cp.async.wait_group 1;");
        } else {
            asm volatile("cp.async.wait_group 0;");
        }
        __syncthreads();

        const float* Kst = Ks + cur*STAGE_W;
        const float* Vst = Vs + cur*STAGE_W;

        float sc[8][4];
#pragma unroll
        for (int ni = 0; ni < 8; ni++)
#pragma unroll
            for (int j = 0; j < 4; j++) sc[ni][j] = 0.f;
#pragma unroll
        for (int ks = 0; ks < 8; ks++) {
#pragma unroll
            for (int ni = 0; ni < 8; ni++) {
                const float* bp = Kst + (ni*8 + gr)*FSTR + ks*8 + gc;
                unsigned b[2] = { __float_as_uint(bp[0]), __float_as_uint(bp[4]) };
                mma_tf32(sc[ni], qa[ks], b);
            }
        }

        const int qrow0 = qt*128 + wid*16 + gr;
        if (kt >= 2*qt) {
#pragma unroll
            for (int ni = 0; ni < 8; ni++) {
                int col = kt*64 + ni*8 + 2*gc;
                if (col     > qrow0)     sc[ni][0] = -1e30f;
                if (col + 1 > qrow0)     sc[ni][1] = -1e30f;
                if (col     > qrow0 + 8) sc[ni][2] = -1e30f;
                if (col + 1 > qrow0 + 8) sc[ni][3] = -1e30f;
            }
        }

        float mx0 = -INFINITY, mx1 = -INFINITY;
#pragma unroll
        for (int ni = 0; ni < 8; ni++) {
            mx0 = fmaxf(mx0, fmaxf(sc[ni][0], sc[ni][1]));
            mx1 = fmaxf(mx1, fmaxf(sc[ni][2], sc[ni][3]));
        }
        mx0 = fmaxf(mx0, __shfl_xor_sync(0xffffffffu, mx0, 1));
        mx0 = fmaxf(mx0, __shfl_xor_sync(0xffffffffu, mx0, 2));
        mx1 = fmaxf(mx1, __shfl_xor_sync(0xffffffffu, mx1, 1));
        mx1 = fmaxf(mx1, __shfl_xor_sync(0xffffffffu, mx1, 2));
        float mn0 = fmaxf(m0, mx0), mn1 = fmaxf(m1, mx1);
        float al0 = ex2(m0 - mn0), al1 = ex2(m1 - mn1);
        m0 = mn0; m1 = mn1;

        float* pr0 = &QP[arow*FSTR];
        float* pr1 = &QP[(arow+8)*FSTR];
        float s0 = 0.f, s1 = 0.f;
#pragma unroll
        for (int ni = 0; ni < 8; ni++) {
            float p00 = ex2(sc[ni][0] - mn0);
            float p01 = ex2(sc[ni][1] - mn0);
            float p10 = ex2(sc[ni][2] - mn1);
            float p11 = ex2(sc[ni][3] - mn1);
            s0 += p00 + p01;
            s1 += p10 + p11;
            int c = ni*8 + 2*gc;
            *(float2*)&pr0[c] = make_float2(__uint_as_float(f2tf32(p00)),
                                            __uint_as_float(f2tf32(p01)));
            *(float2*)&pr1[c] = make_float2(__uint_as_float(f2tf32(p10)),
                                            __uint_as_float(f2tf32(p11)));
        }
        s0 += __shfl_xor_sync(0xffffffffu, s0, 1);
        s0 += __shfl_xor_sync(0xffffffffu, s0, 2);
        s1 += __shfl_xor_sync(0xffffffffu, s1, 1);
        s1 += __shfl_xor_sync(0xffffffffu, s1, 2);
        l0 = l0 * al0 + s0;
        l1 = l1 * al1 + s1;

#pragma unroll
        for (int ni = 0; ni < 8; ni++) {
            o[ni][0] *= al0; o[ni][1] *= al0;
            o[ni][2] *= al1; o[ni][3] *= al1;
        }
        __syncwarp();

#pragma unroll
        for (int ks = 0; ks < 8; ks++) {
            const float* ap = &QP[arow*FSTR + ks*8 + gc];
            unsigned pa[4] = { __float_as_uint(ap[0]),  __float_as_uint(ap[8*FSTR]),
                               __float_as_uint(ap[4]),  __float_as_uint(ap[8*FSTR + 4]) };
#pragma unroll
            for (int ni = 0; ni < 8; ni++) {
                unsigned b[2] = { __float_as_uint(Vst[(ks*8 + gc)*FSTR + ni*8 + gr]),
                                  __float_as_uint(Vst[(ks*8 + gc + 4)*FSTR + ni*8 + gr]) };
                mma_tf32(o[ni], pa, b);
            }
        }
    }

    float inv0 = 1.f / l0, inv1 = 1.f / l1;
    const int b = bh / NH_, h = bh % NH_;
    const int srow0 = qt*128 + wid*16 + gr;
#pragma unroll
    for (int ni = 0; ni < 8; ni++) {
        int col = h*64 + ni*8 + 2*gc;
        *(float2*)(g_attn + (size_t)(b*S_ + srow0) * H_ + col) =
            make_float2(__uint_as_float(f2tf32(o[ni][0]*inv0)),
                        __uint_as_float(f2tf32(o[ni][1]*inv0)));
        *(float2*)(g_attn + (size_t)(b*S_ + srow0 + 8) * H_ + col) =
            make_float2(__uint_as_float(f2tf32(o[ni][2]*inv1)),
                        __uint_as_float(f2tf32(o[ni][3]*inv1)));
    }
}

// ---------------- launch --------------------------------------------------------------
extern "C" void kernel_launch(void* const* d_in, const int* in_sizes, int n_in,
                              void* d_out, int out_size) {
    (void)in_sizes; (void)n_in; (void)out_size;
    const float* x       = (const float*)d_in[0];
    const float* ve      = (const float*)d_in[1];
    const float* Wqkv    = (const float*)d_in[2];
    const float* Wo      = (const float*)d_in[3];
    const float* lambdas = (const float*)d_in[4];
    float* out = (float*)d_out;

    void *p_qkv, *p_attn;
    cudaGetSymbolAddress(&p_qkv,  g_qkv);
    cudaGetSymbolAddress(&p_attn, g_attn);

    static bool attr_done = false;
    if (!attr_done) {
        cudaFuncSetAttribute(flash_v4, cudaFuncAttributeMaxDynamicSharedMemorySize,
                             FLASH_SMEM_BYTES);
        cudaFuncSetAttribute(gemm_v3, cudaFuncAttributeMaxDynamicSharedMemorySize,
                             GEMM_SMEM_BYTES);
        attr_done = true;
    }

    // 1) qkv = x @ W_qkv^T
    gemm_v3<<<dim3(3*H_/128, ROWS_/128), 256, GEMM_SMEM_BYTES>>>(x, Wqkv, (float*)p_qkv,
                                                                 ROWS_, 3*H_, H_);
    // 2) RoPE table
    rope_table_kernel<<<(S_*32 + 255)/256, 256>>>();
    // 3) prep
    prep_kernel<<<(B_*S_*NH_*32 + 255)/256, 256>>>(ve, lambdas);
    // 4) causal flash attention (cp.async pipelined)
    flash_v4<<<dim3(S_/128, B_*NH_), 256, FLASH_SMEM_BYTES>>>();
    // 5) out = attn @ W_o^T
    gemm_v3<<<dim3(H_/128, ROWS_/128), 256, GEMM_SMEM_BYTES>>>((const float*)p_attn, Wo, out,
                                                               ROWS_, H_, H_);
}

// round 8
// speedup vs baseline: 1.1664x; 1.0662x over previous
#include <cuda_runtime.h>
#include <cuda_bf16.h>
#include <math.h>
#include <stdint.h>

// Problem constants
#define B_  2
#define S_  2048
#define H_  1024
#define NH_ 16
#define D_  64
#define ROWS_ (B_*S_)        // 4096
#define EPS_ 1.1920929e-07f
#define QSCALE_ (0.125f * 1.4426950408889634f)   // (1/sqrt(D)) * log2(e)

// ---------------- scratch -------------------------------------------------------------
__device__ float g_qkv[(size_t)ROWS_ * 3 * H_];
__device__ float g_q[(size_t)B_*NH_*S_*D_];
__device__ float g_k[(size_t)B_*NH_*S_*D_];
__device__ float g_v[(size_t)B_*NH_*S_*D_];
__device__ float g_attn[(size_t)ROWS_ * H_];
__device__ float g_x32[(size_t)ROWS_ * H_];      // tf32-pre-rounded GEMM inputs
__device__ float g_w1[(size_t)3*H_ * H_];
__device__ float g_w2[(size_t)H_ * H_];
__device__ float g_cos[S_*32];
__device__ float g_sin[S_*32];

// ---------------- helpers -------------------------------------------------------------
__device__ __forceinline__ unsigned f2tf32(float f) {
    unsigned u;
    asm("cvt.rna.tf32.f32 %0, %1;" : "=r"(u) : "f"(f));
    return u;
}
__device__ __forceinline__ float ex2(float x) {
    float r;
    asm("ex2.approx.f32 %0, %1;" : "=f"(r) : "f"(x));
    return r;
}
__device__ __forceinline__ void mma_tf32(float c[4], const unsigned a[4], const unsigned b[2]) {
    asm volatile(
        "mma.sync.aligned.m16n8k8.row.col.f32.tf32.tf32.f32 "
        "{%0,%1,%2,%3}, {%4,%5,%6,%7}, {%8,%9}, {%0,%1,%2,%3};"
        : "+f"(c[0]), "+f"(c[1]), "+f"(c[2]), "+f"(c[3])
        : "r"(a[0]), "r"(a[1]), "r"(a[2]), "r"(a[3]), "r"(b[0]), "r"(b[1]));
}
__device__ __forceinline__ void cp16(unsigned dst, const void* src) {
    asm volatile("cp.async.cg.shared.global [%0], [%1], 16;" :: "r"(dst), "l"(src));
}
__device__ __forceinline__ uint32_t smem_u32(const void* p) {
    return (uint32_t)__cvta_generic_to_shared(p);
}

// ---------------- elementwise tf32 rounding (once per input tensor) -------------------
__global__ void cvt_tf32_kernel(const float* __restrict__ in, float* __restrict__ out, int n) {
    int i = (blockIdx.x * blockDim.x + threadIdx.x) * 4;
    if (i >= n) return;
    float4 v = *(const float4*)(in + i);
    float4 o;
    o.x = __uint_as_float(f2tf32(v.x));
    o.y = __uint_as_float(f2tf32(v.y));
    o.z = __uint_as_float(f2tf32(v.z));
    o.w = __uint_as_float(f2tf32(v.w));
    *(float4*)(out + i) = o;
}

// ---------------- RoPE table ----------------------------------------------------------
__global__ void rope_table_kernel() {
    int idx = blockIdx.x * blockDim.x + threadIdx.x;
    if (idx >= S_*32) return;
    int s = idx >> 5, j = idx & 31;
    double invf = pow(1.0e-4, (double)j / 32.0);
    float f = (float)s * (float)invf;
    double sn, cs;
    sincos((double)f, &sn, &cs);
    g_cos[idx] = (float)cs;
    g_sin[idx] = (float)sn;
}

// ---------------- tf32 GEMM v4: C[M,N] = A[M,K] * B[N,K]^T ----------------------------
// Inputs pre-rounded to tf32 -> loads are pure cp.async (no LDG/CVT/STS in warp stream).
// 128x128 tile, BK=32, pad-36 rows ([m][k], frag LDS conflict-free), 2 stages,
// 256 thr = 8 warps (4m x 2n), warp tile 32x64. 2 syncs/slab, 32 slabs.
#define GP 36
#define GSLAB (128*GP)                         // words per matrix per stage
#define GEMM_SMEM_BYTES (4*GSLAB*4)            // 73728

__global__ __launch_bounds__(256, 2)
void gemm_v4(const float* __restrict__ A, const float* __restrict__ Bm,
             float* __restrict__ C, int M, int N, int K) {
    extern __shared__ unsigned smg[];
    unsigned* As = smg;                        // [2][128][GP]
    unsigned* Bs = smg + 2*GSLAB;

    const int tid  = threadIdx.x;
    const int lane = tid & 31;
    const int wid  = tid >> 5;
    const int gr   = lane >> 2;
    const int gc   = lane & 3;
    const int bm = blockIdx.y * 128;
    const int bn = blockIdx.x * 128;
    const int wm = (wid >> 1) * 32;
    const int wn = (wid & 1) * 64;

    const int lr = tid >> 2;                   // 0..63
    const int lc = (tid & 3) << 2;             // 0,4,8,12
    const unsigned as_u32 = smem_u32(As);
    const unsigned bs_u32 = smem_u32(Bs);

    auto load_slab = [&](int t, int s) {
        const int k0 = t << 5;
        const unsigned ad = as_u32 + (unsigned)(s*GSLAB*4);
        const unsigned bd = bs_u32 + (unsigned)(s*GSLAB*4);
#pragma unroll
        for (int rr = 0; rr < 2; rr++) {
            int r = lr + rr*64;
#pragma unroll
            for (int cc = 0; cc < 2; cc++) {
                int c = lc + cc*16;
                unsigned off = (unsigned)((r*GP + c) * 4);
                cp16(ad + off, A  + (size_t)(bm + r) * K + k0 + c);
                cp16(bd + off, Bm + (size_t)(bn + r) * K + k0 + c);
            }
        }
        asm volatile("cp.async.commit_group;");
    };

    float acc[2][8][4];
#pragma unroll
    for (int mi = 0; mi < 2; mi++)
#pragma unroll
        for (int ni = 0; ni < 8; ni++)
#pragma unroll
            for (int j = 0; j < 4; j++) acc[mi][ni][j] = 0.f;

    load_slab(0, 0);

    const int T = K >> 5;                      // 32 slabs
    for (int t = 0; t < T; t++) {
        const int cur = t & 1;
        __syncthreads();                       // stage cur^1 reads (iter t-1) done
        if (t + 1 < T) {
            load_slab(t + 1, cur ^ 1);
            asm volatile("cp.async.wait_group 1;");
        } else {
            asm volatile("cp.async.wait_group 0;");
        }
        __syncthreads();                       // stage cur visible to all warps

        const unsigned* Ab = As + cur*GSLAB;
        const unsigned* Bb = Bs + cur*GSLAB;
#pragma unroll
        for (int ks = 0; ks < 4; ks++) {
            const int kb = ks * 8;
            unsigned a[2][4];
#pragma unroll
            for (int mi = 0; mi < 2; mi++) {
                const unsigned* ap = &Ab[(wm + mi*16 + gr)*GP + kb + gc];
                a[mi][0] = ap[0];
                a[mi][1] = ap[8*GP];
                a[mi][2] = ap[4];
                a[mi][3] = ap[8*GP + 4];
            }
#pragma unroll
            for (int ni = 0; ni < 8; ni++) {
                const unsigned* bp = &Bb[(wn + ni*8 + gr)*GP + kb + gc];
                unsigned b[2] = { bp[0], bp[4] };
                mma_tf32(acc[0][ni], a[0], b);
                mma_tf32(acc[1][ni], a[1], b);
            }
        }
    }

#pragma unroll
    for (int mi = 0; mi < 2; mi++) {
        int m0 = bm + wm + mi*16 + gr;
#pragma unroll
        for (int ni = 0; ni < 8; ni++) {
            int n = bn + wn + ni*8 + 2*gc;
            *(float2*)(C + (size_t)m0 * N + n)       = make_float2(acc[mi][ni][0], acc[mi][ni][1]);
            *(float2*)(C + (size_t)(m0 + 8) * N + n) = make_float2(acc[mi][ni][2], acc[mi][ni][3]);
        }
    }
}

// ---------------- prep (unchanged) ----------------------------------------------------
__global__ void prep_kernel(const float* __restrict__ ve, const float* __restrict__ lambdas) {
    int gtid = blockIdx.x * blockDim.x + threadIdx.x;
    int warp = gtid >> 5;
    int lane = gtid & 31;
    if (warp >= B_*S_*NH_) return;
    int h = warp % NH_;
    int s = (warp / NH_) % S_;
    int b = warp / (NH_ * S_);

    const float* row = g_qkv + (size_t)(b*S_ + s) * (3*H_);
    float q1 = row[h*64 + lane],          q2 = row[h*64 + 32 + lane];
    float k1 = row[H_ + h*64 + lane],     k2 = row[H_ + h*64 + 32 + lane];
    float v1 = row[2*H_ + h*64 + lane],   v2 = row[2*H_ + h*64 + 32 + lane];

    float sq = q1*q1 + q2*q2;
    float sk = k1*k1 + k2*k2;
#pragma unroll
    for (int o = 16; o; o >>= 1) {
        sq += __shfl_xor_sync(0xffffffffu, sq, o);
        sk += __shfl_xor_sync(0xffffffffu, sk, o);
    }
    float rq = rsqrtf(sq * (1.f/64.f) + EPS_);
    float rk = rsqrtf(sk * (1.f/64.f) + EPS_);
    q1 *= rq; q2 *= rq; k1 *= rk; k2 *= rk;

    float c  = g_cos[s*32 + lane];
    float sn = g_sin[s*32 + lane];
    float qo1 = (q1*c + q2*sn) * QSCALE_;
    float qo2 = (q2*c - q1*sn) * QSCALE_;
    float ko1 = k1*c + k2*sn, ko2 = k2*c - k1*sn;

    float l0 = lambdas[0], l1 = lambdas[1];
    const float* verow = ve + (size_t)(b*S_ + s) * H_ + h*64;
    float vo1 = l0*v1 + l1*verow[lane];
    float vo2 = l0*v2 + l1*verow[32 + lane];

    size_t o = ((size_t)(b*NH_ + h) * S_ + s) * 64 + lane;
    g_q[o]    = __uint_as_float(f2tf32(qo1));
    g_q[o+32] = __uint_as_float(f2tf32(qo2));
    g_k[o]    = __uint_as_float(f2tf32(ko1));
    g_k[o+32] = __uint_as_float(f2tf32(ko2));
    g_v[o]    = __uint_as_float(f2tf32(vo1));
    g_v[o+32] = __uint_as_float(f2tf32(vo2));
}

// ---------------- flash attention v5 (v4 minus P cvt instructions) --------------------
#define FSTR 68
#define STAGE_W (64*FSTR)
#define FLASH_SMEM_BYTES ((128*FSTR + 4*STAGE_W)*4)   // 104448

__global__ __launch_bounds__(256, 2)
void flash_v5() {
    extern __shared__ float sm[];
    float* QP = sm;
    float* Ks = sm + 128*FSTR;
    float* Vs = Ks + 2*STAGE_W;

    const int tid  = threadIdx.x;
    const int lane = tid & 31;
    const int wid  = tid >> 5;
    const int gr   = lane >> 2;
    const int gc   = lane & 3;
    const int qt   = gridDim.x - 1 - blockIdx.x;
    const int bh   = blockIdx.y;
    const int arow = wid*16 + gr;

    const unsigned ks_u32 = smem_u32(Ks);
    const unsigned vs_u32 = smem_u32(Vs);
    const float* Kbase = g_k + (size_t)bh * S_ * 64;
    const float* Vbase = g_v + (size_t)bh * S_ * 64;
    const int ktmax = 2*qt + 1;

    const int cr = tid >> 4;
    const int cc = (tid & 15) << 2;

    {
        const float* Kg = Kbase;  const float* Vg = Vbase;
#pragma unroll
        for (int j = 0; j < 4; j++) {
            int r = cr + j*16;
            unsigned off = (unsigned)((r*FSTR + cc) * 4);
            cp16(ks_u32 + off, Kg + r*64 + cc);
            cp16(vs_u32 + off, Vg + r*64 + cc);
        }
        asm volatile("cp.async.commit_group;");
    }

    const float* Qg = g_q + ((size_t)bh * S_ + qt*128) * 64;
    for (int i = tid; i < 2048; i += 256) {
        int r = i >> 4, dc = (i & 15) << 2;
        *(float4*)&QP[r*FSTR + dc] = *(const float4*)(Qg + r*64 + dc);
    }
    __syncthreads();

    unsigned qa[8][4];
#pragma unroll
    for (int ks = 0; ks < 8; ks++) {
        const float* ap = &QP[arow*FSTR + ks*8 + gc];
        qa[ks][0] = __float_as_uint(ap[0]);
        qa[ks][1] = __float_as_uint(ap[8*FSTR]);
        qa[ks][2] = __float_as_uint(ap[4]);
        qa[ks][3] = __float_as_uint(ap[8*FSTR + 4]);
    }

    float o[8][4];
#pragma unroll
    for (int ni = 0; ni < 8; ni++)
#pragma unroll
        for (int j = 0; j < 4; j++) o[ni][j] = 0.f;
    float m0 = -INFINITY, m1 = -INFINITY, l0 = 0.f, l1 = 0.f;

    for (int kt = 0; kt <= ktmax; kt++) {
        const int cur = kt & 1;
        __syncthreads();

        if (kt < ktmax) {
            const int nst = cur ^ 1;
            const float* Kg = Kbase + (size_t)(kt+1)*64*64;
            const float* Vg = Vbase + (size_t)(kt+1)*64*64;
            unsigned kd = ks_u32 + (unsigned)(nst*STAGE_W*4);
            unsigned vd = vs_u32 + (unsigned)(nst*STAGE_W*4);
#pragma unroll
            for (int j = 0; j < 4; j++) {
                int r = cr + j*16;
                unsigned off = (unsigned)((r*FSTR + cc) * 4);
                cp16(kd + off, Kg + r*64 + cc);
                cp16(vd + off, Vg + r*64 + cc);
            }
            asm volatile("cp.async.commit_group;");
            asm volatile("cp.async.wait_group 1;");
        } else {
            asm volatile("cp.async.wait_group 0;");
        }
        __syncthreads();

        const float* Kst = Ks + cur*STAGE_W;
        const float* Vst = Vs + cur*STAGE_W;

        float sc[8][4];
#pragma unroll
        for (int ni = 0; ni < 8; ni++)
#pragma unroll
            for (int j = 0; j < 4; j++) sc[ni][j] = 0.f;
#pragma unroll
        for (int ks = 0; ks < 8; ks++) {
#pragma unroll
            for (int ni = 0; ni < 8; ni++) {
                const float* bp = Kst + (ni*8 + gr)*FSTR + ks*8 + gc;
                unsigned b[2] = { __float_as_uint(bp[0]), __float_as_uint(bp[4]) };
                mma_tf32(sc[ni], qa[ks], b);
            }
        }

        const int qrow0 = qt*128 + wid*16 + gr;
        if (kt >= 2*qt) {
#pragma unroll
            for (int ni = 0; ni < 8; ni++) {
                int col = kt*64 + ni*8 + 2*gc;
                if (col     > qrow0)     sc[ni][0] = -1e30f;
                if (col + 1 > qrow0)     sc[ni][1] = -1e30f;
                if (col     > qrow0 + 8) sc[ni][2] = -1e30f;
                if (col + 1 > qrow0 + 8) sc[ni][3] = -1e30f;
            }
        }

        float mx0 = -INFINITY, mx1 = -INFINITY;
#pragma unroll
        for (int ni = 0; ni < 8; ni++) {
            mx0 = fmaxf(mx0, fmaxf(sc[ni][0], sc[ni][1]));
            mx1 = fmaxf(mx1, fmaxf(sc[ni][2], sc[ni][3]));
        }
        mx0 = fmaxf(mx0, __shfl_xor_sync(0xffffffffu, mx0, 1));
        mx0 = fmaxf(mx0, __shfl_xor_sync(0xffffffffu, mx0, 2));
        mx1 = fmaxf(mx1, __shfl_xor_sync(0xffffffffu, mx1, 1));
        mx1 = fmaxf(mx1, __shfl_xor_sync(0xffffffffu, mx1, 2));
        float mn0 = fmaxf(m0, mx0), mn1 = fmaxf(m1, mx1);
        float al0 = ex2(m0 - mn0), al1 = ex2(m1 - mn1);
        m0 = mn0; m1 = mn1;

        float* pr0 = &QP[arow*FSTR];
        float* pr1 = &QP[(arow+8)*FSTR];
        float s0 = 0.f, s1 = 0.f;
#pragma unroll
        for (int ni = 0; ni < 8; ni++) {
            float p00 = ex2(sc[ni][0] - mn0);
            float p01 = ex2(sc[ni][1] - mn0);
            float p10 = ex2(sc[ni][2] - mn1);
            float p11 = ex2(sc[ni][3] - mn1);
            s0 += p00 + p01;
            s1 += p10 + p11;
            int c = ni*8 + 2*gc;
            // raw fp32: mma.sync truncates to tf32 mantissa in HW (saves 4 CVT here)
            *(float2*)&pr0[c] = make_float2(p00, p01);
            *(float2*)&pr1[c] = make_float2(p10, p11);
        }
        s0 += __shfl_xor_sync(0xffffffffu, s0, 1);
        s0 += __shfl_xor_sync(0xffffffffu, s0, 2);
        s1 += __shfl_xor_sync(0xffffffffu, s1, 1);
        s1 += __shfl_xor_sync(0xffffffffu, s1, 2);
        l0 = l0 * al0 + s0;
        l1 = l1 * al1 + s1;

#pragma unroll
        for (int ni = 0; ni < 8; ni++) {
            o[ni][0] *= al0; o[ni][1] *= al0;
            o[ni][2] *= al1; o[ni][3] *= al1;
        }
        __syncwarp();

#pragma unroll
        for (int ks = 0; ks < 8; ks++) {
            const float* ap = &QP[arow*FSTR + ks*8 + gc];
            unsigned pa[4] = { __float_as_uint(ap[0]),  __float_as_uint(ap[8*FSTR]),
                               __float_as_uint(ap[4]),  __float_as_uint(ap[8*FSTR + 4]) };
#pragma unroll
            for (int ni = 0; ni < 8; ni++) {
                unsigned b[2] = { __float_as_uint(Vst[(ks*8 + gc)*FSTR + ni*8 + gr]),
                                  __float_as_uint(Vst[(ks*8 + gc + 4)*FSTR + ni*8 + gr]) };
                mma_tf32(o[ni], pa, b);
            }
        }
    }

    float inv0 = 1.f / l0, inv1 = 1.f / l1;
    const int b = bh / NH_, h = bh % NH_;
    const int srow0 = qt*128 + wid*16 + gr;
#pragma unroll
    for (int ni = 0; ni < 8; ni++) {
        int col = h*64 + ni*8 + 2*gc;
        // attn feeds the Wo GEMM via cp.async -> keep rna tf32 rounding here
        *(float2*)(g_attn + (size_t)(b*S_ + srow0) * H_ + col) =
            make_float2(__uint_as_float(f2tf32(o[ni][0]*inv0)),
                        __uint_as_float(f2tf32(o[ni][1]*inv0)));
        *(float2*)(g_attn + (size_t)(b*S_ + srow0 + 8) * H_ + col) =
            make_float2(__uint_as_float(f2tf32(o[ni][2]*inv1)),
                        __uint_as_float(f2tf32(o[ni][3]*inv1)));
    }
}

// ---------------- launch --------------------------------------------------------------
extern "C" void kernel_launch(void* const* d_in, const int* in_sizes, int n_in,
                              void* d_out, int out_size) {
    (void)in_sizes; (void)n_in; (void)out_size;
    const float* x       = (const float*)d_in[0];
    const float* ve      = (const float*)d_in[1];
    const float* Wqkv    = (const float*)d_in[2];
    const float* Wo      = (const float*)d_in[3];
    const float* lambdas = (const float*)d_in[4];
    float* out = (float*)d_out;

    void *p_qkv, *p_attn, *p_x32, *p_w1, *p_w2;
    cudaGetSymbolAddress(&p_qkv,  g_qkv);
    cudaGetSymbolAddress(&p_attn, g_attn);
    cudaGetSymbolAddress(&p_x32,  g_x32);
    cudaGetSymbolAddress(&p_w1,   g_w1);
    cudaGetSymbolAddress(&p_w2,   g_w2);

    static bool attr_done = false;
    if (!attr_done) {
        cudaFuncSetAttribute(flash_v5, cudaFuncAttributeMaxDynamicSharedMemorySize,
                             FLASH_SMEM_BYTES);
        cudaFuncSetAttribute(gemm_v4, cudaFuncAttributeMaxDynamicSharedMemorySize,
                             GEMM_SMEM_BYTES);
        attr_done = true;
    }

    // 0) tf32-pre-round GEMM inputs (cp.async path does raw 16B copies)
    cvt_tf32_kernel<<<ROWS_*H_/4/256,  256>>>(x,    (float*)p_x32, ROWS_*H_);
    cvt_tf32_kernel<<<3*H_*H_/4/256,   256>>>(Wqkv, (float*)p_w1,  3*H_*H_);
    cvt_tf32_kernel<<<H_*H_/4/256,     256>>>(Wo,   (float*)p_w2,  H_*H_);
    // 1) qkv = x @ W_qkv^T
    gemm_v4<<<dim3(3*H_/128, ROWS_/128), 256, GEMM_SMEM_BYTES>>>(
        (const float*)p_x32, (const float*)p_w1, (float*)p_qkv, ROWS_, 3*H_, H_);
    // 2) RoPE table
    rope_table_kernel<<<(S_*32 + 255)/256, 256>>>();
    // 3) prep
    prep_kernel<<<(B_*S_*NH_*32 + 255)/256, 256>>>(ve, lambdas);
    // 4) causal flash attention
    flash_v5<<<dim3(S_/128, B_*NH_), 256, FLASH_SMEM_BYTES>>>();
    // 5) out = attn @ W_o^T
    gemm_v4<<<dim3(H_/128, ROWS_/128), 256, GEMM_SMEM_BYTES>>>(
        (const float*)p_attn, (const float*)p_w2, out, ROWS_, H_, H_);
}

// round 9
// speedup vs baseline: 1.2145x; 1.0412x over previous
#include <cuda_runtime.h>
#include <cuda_bf16.h>
#include <math.h>
#include <stdint.h>

// Problem constants
#define B_  2
#define S_  2048
#define H_  1024
#define NH_ 16
#define D_  64
#define ROWS_ (B_*S_)        // 4096
#define EPS_ 1.1920929e-07f
#define QSCALE_ (0.125f * 1.4426950408889634f)   // (1/sqrt(D)) * log2(e)

// K-dim permutation within each 8-group: k -> 2*(k&3) + (k>>2 & 1)
// stored order per group: k = 0,4,1,5,2,6,3,7  (mma pairs (k,k+4) adjacent)

// ---------------- scratch -------------------------------------------------------------
__device__ float g_qkv[(size_t)ROWS_ * 3 * H_];   // natural
__device__ float g_q[(size_t)B_*NH_*S_*D_];       // d-permuted
__device__ float g_k[(size_t)B_*NH_*S_*D_];       // d-permuted
__device__ float g_v[(size_t)B_*NH_*S_*D_];       // natural
__device__ float g_attn[(size_t)ROWS_ * H_];      // h-permuted (K of Wo gemm)
__device__ float g_x32[(size_t)ROWS_ * H_];       // tf32 + k-permuted
__device__ float g_w1[(size_t)3*H_ * H_];         // tf32 + k-permuted
__device__ float g_w2[(size_t)H_ * H_];           // tf32 + k-permuted
__device__ float g_cos[S_*32];
__device__ float g_sin[S_*32];

// ---------------- helpers -------------------------------------------------------------
__device__ __forceinline__ unsigned f2tf32(float f) {
    unsigned u;
    asm("cvt.rna.tf32.f32 %0, %1;" : "=r"(u) : "f"(f));
    return u;
}
__device__ __forceinline__ float ex2(float x) {
    float r;
    asm("ex2.approx.f32 %0, %1;" : "=f"(r) : "f"(x));
    return r;
}
__device__ __forceinline__ void mma_tf32(float c[4], const unsigned a[4], const unsigned b[2]) {
    asm volatile(
        "mma.sync.aligned.m16n8k8.row.col.f32.tf32.tf32.f32 "
        "{%0,%1,%2,%3}, {%4,%5,%6,%7}, {%8,%9}, {%0,%1,%2,%3};"
        : "+f"(c[0]), "+f"(c[1]), "+f"(c[2]), "+f"(c[3])
        : "r"(a[0]), "r"(a[1]), "r"(a[2]), "r"(a[3]), "r"(b[0]), "r"(b[1]));
}
__device__ __forceinline__ void cp16(unsigned dst, const void* src) {
    asm volatile("cp.async.cg.shared.global [%0], [%1], 16;" :: "r"(dst), "l"(src));
}
__device__ __forceinline__ uint32_t smem_u32(const void* p) {
    return (uint32_t)__cvta_generic_to_shared(p);
}

// ---------------- tf32 rounding + k-pair permutation (8 elems / thread) ---------------
__global__ void cvt_tf32_perm_kernel(const float* __restrict__ in, float* __restrict__ out,
                                     int n) {
    int i = (blockIdx.x * blockDim.x + threadIdx.x) * 8;
    if (i >= n) return;
    float4 v0 = *(const float4*)(in + i);
    float4 v1 = *(const float4*)(in + i + 4);
    float4 o0, o1;   // order: k0,k4,k1,k5 | k2,k6,k3,k7
    o0.x = __uint_as_float(f2tf32(v0.x));
    o0.y = __uint_as_float(f2tf32(v1.x));
    o0.z = __uint_as_float(f2tf32(v0.y));
    o0.w = __uint_as_float(f2tf32(v1.y));
    o1.x = __uint_as_float(f2tf32(v0.z));
    o1.y = __uint_as_float(f2tf32(v1.z));
    o1.z = __uint_as_float(f2tf32(v0.w));
    o1.w = __uint_as_float(f2tf32(v1.w));
    *(float4*)(out + i)     = o0;
    *(float4*)(out + i + 4) = o1;
}

// ---------------- RoPE table ----------------------------------------------------------
__global__ void rope_table_kernel() {
    int idx = blockIdx.x * blockDim.x + threadIdx.x;
    if (idx >= S_*32) return;
    int s = idx >> 5, j = idx & 31;
    double invf = pow(1.0e-4, (double)j / 32.0);
    float f = (float)s * (float)invf;
    double sn, cs;
    sincos((double)f, &sn, &cs);
    g_cos[idx] = (float)cs;
    g_sin[idx] = (float)sn;
}

// ---------------- tf32 GEMM v5: C[M,N] = A[M,K] * B[N,K]^T ----------------------------
// Inputs tf32 + k-permuted in gmem -> cp.async contiguous AND uint2 fragment loads.
// GSTR=40 (==8 mod 32): LDS.64 frags conflict-free per half-warp phase.
// 128x128 tile, BK=32, 2 stages, 256 thr = 8 warps (4m x 2n), warp tile 32x64.
#define GSTR 40
#define GSLAB (128*GSTR)
#define GEMM_SMEM_BYTES (4*GSLAB*4)            // 81920

__global__ __launch_bounds__(256, 2)
void gemm_v5(const float* __restrict__ A, const float* __restrict__ Bm,
             float* __restrict__ C, int M, int N, int K) {
    extern __shared__ unsigned smg[];
    unsigned* As = smg;                        // [2][128][GSTR]
    unsigned* Bs = smg + 2*GSLAB;

    const int tid  = threadIdx.x;
    const int lane = tid & 31;
    const int wid  = tid >> 5;
    const int gr   = lane >> 2;
    const int gc   = lane & 3;
    const int bm = blockIdx.y * 128;
    const int bn = blockIdx.x * 128;
    const int wm = (wid >> 1) * 32;
    const int wn = (wid & 1) * 64;

    const int lr = tid >> 2;                   // 0..63
    const int lq = (tid & 3) * 2;              // chunk base 0,2,4,6
    const unsigned as_u32 = smem_u32(As);
    const unsigned bs_u32 = smem_u32(Bs);

    auto load_slab = [&](int t, int s) {
        const int k0 = t << 5;
        const unsigned ad = as_u32 + (unsigned)(s*GSLAB*4);
        const unsigned bd = bs_u32 + (unsigned)(s*GSLAB*4);
#pragma unroll
        for (int rr = 0; rr < 2; rr++) {
            int r = lr + rr*64;
#pragma unroll
            for (int q = 0; q < 2; q++) {
                int c = (lq + q) * 4;          // word offset in slab row
                unsigned off = (unsigned)((r*GSTR + c) * 4);
                cp16(ad + off, A  + (size_t)(bm + r) * K + k0 + c);
                cp16(bd + off, Bm + (size_t)(bn + r) * K + k0 + c);
            }
        }
        asm volatile("cp.async.commit_group;");
    };

    float acc[2][8][4];
#pragma unroll
    for (int mi = 0; mi < 2; mi++)
#pragma unroll
        for (int ni = 0; ni < 8; ni++)
#pragma unroll
            for (int j = 0; j < 4; j++) acc[mi][ni][j] = 0.f;

    load_slab(0, 0);

    const int T = K >> 5;
    for (int t = 0; t < T; t++) {
        const int cur = t & 1;
        __syncthreads();
        if (t + 1 < T) {
            load_slab(t + 1, cur ^ 1);
            asm volatile("cp.async.wait_group 1;");
        } else {
            asm volatile("cp.async.wait_group 0;");
        }
        __syncthreads();

        const unsigned* Ab = As + cur*GSLAB;
        const unsigned* Bb = Bs + cur*GSLAB;
#pragma unroll
        for (int ks = 0; ks < 4; ks++) {
            const int kb = ks*8 + 2*gc;        // permuted pair base
            unsigned a[2][4];
#pragma unroll
            for (int mi = 0; mi < 2; mi++) {
                uint2 lo = *(const uint2*)&Ab[(wm + mi*16 + gr)*GSTR + kb];
                uint2 hi = *(const uint2*)&Ab[(wm + mi*16 + 8 + gr)*GSTR + kb];
                a[mi][0] = lo.x; a[mi][1] = hi.x; a[mi][2] = lo.y; a[mi][3] = hi.y;
            }
#pragma unroll
            for (int ni = 0; ni < 8; ni++) {
                uint2 bb = *(const uint2*)&Bb[(wn + ni*8 + gr)*GSTR + kb];
                unsigned b[2] = { bb.x, bb.y };
                mma_tf32(acc[0][ni], a[0], b);
                mma_tf32(acc[1][ni], a[1], b);
            }
        }
    }

#pragma unroll
    for (int mi = 0; mi < 2; mi++) {
        int m0 = bm + wm + mi*16 + gr;
#pragma unroll
        for (int ni = 0; ni < 8; ni++) {
            int n = bn + wn + ni*8 + 2*gc;
            *(float2*)(C + (size_t)m0 * N + n)       = make_float2(acc[mi][ni][0], acc[mi][ni][1]);
            *(float2*)(C + (size_t)(m0 + 8) * N + n) = make_float2(acc[mi][ni][2], acc[mi][ni][3]);
        }
    }
}

// ---------------- prep: RMSNorm+RoPE, lambda-mix; q/k stored d-permuted ---------------
__global__ void prep_kernel(const float* __restrict__ ve, const float* __restrict__ lambdas) {
    int gtid = blockIdx.x * blockDim.x + threadIdx.x;
    int warp = gtid >> 5;
    int lane = gtid & 31;
    if (warp >= B_*S_*NH_) return;
    int h = warp % NH_;
    int s = (warp / NH_) % S_;
    int b = warp / (NH_ * S_);

    const float* row = g_qkv + (size_t)(b*S_ + s) * (3*H_);
    float q1 = row[h*64 + lane],          q2 = row[h*64 + 32 + lane];
    float k1 = row[H_ + h*64 + lane],     k2 = row[H_ + h*64 + 32 + lane];
    float v1 = row[2*H_ + h*64 + lane],   v2 = row[2*H_ + h*64 + 32 + lane];

    float sq = q1*q1 + q2*q2;
    float sk = k1*k1 + k2*k2;
#pragma unroll
    for (int o = 16; o; o >>= 1) {
        sq += __shfl_xor_sync(0xffffffffu, sq, o);
        sk += __shfl_xor_sync(0xffffffffu, sk, o);
    }
    float rq = rsqrtf(sq * (1.f/64.f) + EPS_);
    float rk = rsqrtf(sk * (1.f/64.f) + EPS_);
    q1 *= rq; q2 *= rq; k1 *= rk; k2 *= rk;

    float c  = g_cos[s*32 + lane];
    float sn = g_sin[s*32 + lane];
    float qo1 = (q1*c + q2*sn) * QSCALE_;
    float qo2 = (q2*c - q1*sn) * QSCALE_;
    float ko1 = k1*c + k2*sn, ko2 = k2*c - k1*sn;

    float l0 = lambdas[0], l1 = lambdas[1];
    const float* verow = ve + (size_t)(b*S_ + s) * H_ + h*64;
    float vo1 = l0*v1 + l1*verow[lane];
    float vo2 = l0*v2 + l1*verow[32 + lane];

    size_t ob = ((size_t)(b*NH_ + h) * S_ + s) * 64;
    // permuted positions for d=lane and d=lane+32
    int j    = lane & 7;
    int pbase = (lane >> 3) * 8 + 2*(j & 3) + (j >> 2);
    int pos1 = pbase;          // group g = lane>>3
    int pos2 = pbase + 32;     // group g+4
    g_q[ob + pos1] = __uint_as_float(f2tf32(qo1));
    g_q[ob + pos2] = __uint_as_float(f2tf32(qo2));
    g_k[ob + pos1] = __uint_as_float(f2tf32(ko1));
    g_k[ob + pos2] = __uint_as_float(f2tf32(ko2));
    g_v[ob + lane]      = __uint_as_float(f2tf32(vo1));   // V natural
    g_v[ob + lane + 32] = __uint_as_float(f2tf32(vo2));
}

// ---------------- flash attention v6: permuted Q/K/P -> uint2 frags -------------------
// FSTR=72 (==8 mod 32): uint2 Q/K/P frags + scalar V frags all conflict-free.
#define FSTR 72
#define STAGE_W (64*FSTR)
#define FLASH_SMEM_BYTES ((128*FSTR + 4*STAGE_W)*4)   // 110592

__global__ __launch_bounds__(256, 2)
void flash_v6() {
    extern __shared__ float sm[];
    float* QP = sm;                    // 128 x 72 (Q d-permuted; later P n-permuted)
    float* Ks = sm + 128*FSTR;         // 2 x 64 x 72 (d-permuted)
    float* Vs = Ks + 2*STAGE_W;        // 2 x 64 x 72 (natural)

    const int tid  = threadIdx.x;
    const int lane = tid & 31;
    const int wid  = tid >> 5;
    const int gr   = lane >> 2;
    const int gc   = lane & 3;
    const int qt   = gridDim.x - 1 - blockIdx.x;
    const int bh   = blockIdx.y;
    const int arow = wid*16 + gr;

    const unsigned ks_u32 = smem_u32(Ks);
    const unsigned vs_u32 = smem_u32(Vs);
    const float* Kbase = g_k + (size_t)bh * S_ * 64;
    const float* Vbase = g_v + (size_t)bh * S_ * 64;
    const int ktmax = 2*qt + 1;

    const int cr = tid >> 4;
    const int cc = (tid & 15) << 2;

    {
#pragma unroll
        for (int j = 0; j < 4; j++) {
            int r = cr + j*16;
            unsigned off = (unsigned)((r*FSTR + cc) * 4);
            cp16(ks_u32 + off, Kbase + r*64 + cc);
            cp16(vs_u32 + off, Vbase + r*64 + cc);
        }
        asm volatile("cp.async.commit_group;");
    }

    const float* Qg = g_q + ((size_t)bh * S_ + qt*128) * 64;
    for (int i = tid; i < 2048; i += 256) {
        int r = i >> 4, dc = (i & 15) << 2;
        *(float4*)&QP[r*FSTR + dc] = *(const float4*)(Qg + r*64 + dc);
    }
    __syncthreads();

    unsigned qa[8][4];
#pragma unroll
    for (int ks = 0; ks < 8; ks++) {
        uint2 lo = *(const uint2*)&QP[arow*FSTR + ks*8 + 2*gc];
        uint2 hi = *(const uint2*)&QP[(arow+8)*FSTR + ks*8 + 2*gc];
        qa[ks][0] = lo.x; qa[ks][1] = hi.x; qa[ks][2] = lo.y; qa[ks][3] = hi.y;
    }

    float o[8][4];
#pragma unroll
    for (int ni = 0; ni < 8; ni++)
#pragma unroll
        for (int j = 0; j < 4; j++) o[ni][j] = 0.f;
    float m0 = -INFINITY, m1 = -INFINITY, l0 = 0.f, l1 = 0.f;

    for (int kt = 0; kt <= ktmax; kt++) {
        const int cur = kt & 1;
        __syncthreads();

        if (kt < ktmax) {
            const int nst = cur ^ 1;
            const float* Kg = Kbase + (size_t)(kt+1)*64*64;
            const float* Vg = Vbase + (size_t)(kt+1)*64*64;
            unsigned kd = ks_u32 + (unsigned)(nst*STAGE_W*4);
            unsigned vd = vs_u32 + (unsigned)(nst*STAGE_W*4);
#pragma unroll
            for (int j = 0; j < 4; j++) {
                int r = cr + j*16;
                unsigned off = (unsigned)((r*FSTR + cc) * 4);
                cp16(kd + off, Kg + r*64 + cc);
                cp16(vd + off, Vg + r*64 + cc);
            }
            asm volatile("cp.async.commit_group;");
            asm volatile("cp.async.wait_group 1;");
        } else {
            asm volatile("cp.async.wait_group 0;");
        }
        __syncthreads();

        const float* Kst = Ks + cur*STAGE_W;
        const float* Vst = Vs + cur*STAGE_W;

        // S = Q K^T  (uint2 b-frags from permuted K)
        float sc[8][4];
#pragma unroll
        for (int ni = 0; ni < 8; ni++)
#pragma unroll
            for (int j = 0; j < 4; j++) sc[ni][j] = 0.f;
#pragma unroll
        for (int ks = 0; ks < 8; ks++) {
#pragma unroll
            for (int ni = 0; ni < 8; ni++) {
                uint2 bb = *(const uint2*)&Kst[(ni*8 + gr)*FSTR + ks*8 + 2*gc];
                unsigned b[2] = { bb.x, bb.y };
                mma_tf32(sc[ni], qa[ks], b);
            }
        }

        const int qrow0 = qt*128 + wid*16 + gr;
        if (kt >= 2*qt) {
#pragma unroll
            for (int ni = 0; ni < 8; ni++) {
                int col = kt*64 + ni*8 + 2*gc;
                if (col     > qrow0)     sc[ni][0] = -1e30f;
                if (col + 1 > qrow0)     sc[ni][1] = -1e30f;
                if (col     > qrow0 + 8) sc[ni][2] = -1e30f;
                if (col + 1 > qrow0 + 8) sc[ni][3] = -1e30f;
            }
        }

        float mx0 = -INFINITY, mx1 = -INFINITY;
#pragma unroll
        for (int ni = 0; ni < 8; ni++) {
            mx0 = fmaxf(mx0, fmaxf(sc[ni][0], sc[ni][1]));
            mx1 = fmaxf(mx1, fmaxf(sc[ni][2], sc[ni][3]));
        }
        mx0 = fmaxf(mx0, __shfl_xor_sync(0xffffffffu, mx0, 1));
        mx0 = fmaxf(mx0, __shfl_xor_sync(0xffffffffu, mx0, 2));
        mx1 = fmaxf(mx1, __shfl_xor_sync(0xffffffffu, mx1, 1));
        mx1 = fmaxf(mx1, __shfl_xor_sync(0xffffffffu, mx1, 2));
        float mn0 = fmaxf(m0, mx0), mn1 = fmaxf(m1, mx1);
        float al0 = ex2(m0 - mn0), al1 = ex2(m1 - mn1);
        m0 = mn0; m1 = mn1;

        // P stored n-permuted: cols (pp, pp+2) within the ni-group
        const int pp = (gc < 2) ? 4*gc : 4*gc - 7;
        float* pr0 = &QP[arow*FSTR];
        float* pr1 = &QP[(arow+8)*FSTR];
        float s0 = 0.f, s1 = 0.f;
#pragma unroll
        for (int ni = 0; ni < 8; ni++) {
            float p00 = ex2(sc[ni][0] - mn0);
            float p01 = ex2(sc[ni][1] - mn0);
            float p10 = ex2(sc[ni][2] - mn1);
            float p11 = ex2(sc[ni][3] - mn1);
            s0 += p00 + p01;
            s1 += p10 + p11;
            int c = ni*8 + pp;
            pr0[c]   = p00;  pr0[c+2] = p01;
            pr1[c]   = p10;  pr1[c+2] = p11;
        }
        s0 += __shfl_xor_sync(0xffffffffu, s0, 1);
        s0 += __shfl_xor_sync(0xffffffffu, s0, 2);
        s1 += __shfl_xor_sync(0xffffffffu, s1, 1);
        s1 += __shfl_xor_sync(0xffffffffu, s1, 2);
        l0 = l0 * al0 + s0;
        l1 = l1 * al1 + s1;

#pragma unroll
        for (int ni = 0; ni < 8; ni++) {
            o[ni][0] *= al0; o[ni][1] *= al0;
            o[ni][2] *= al1; o[ni][3] *= al1;
        }
        __syncwarp();

        // O += P V  (uint2 a-frags from permuted P; scalar V b-frags)
#pragma unroll
        for (int ks = 0; ks < 8; ks++) {
            uint2 plo = *(const uint2*)&QP[arow*FSTR + ks*8 + 2*gc];
            uint2 phi = *(const uint2*)&QP[(arow+8)*FSTR + ks*8 + 2*gc];
            unsigned pa[4] = { plo.x, phi.x, plo.y, phi.y };
#pragma unroll
            for (int ni = 0; ni < 8; ni++) {
                unsigned b[2] = { __float_as_uint(Vst[(ks*8 + gc)*FSTR + ni*8 + gr]),
                                  __float_as_uint(Vst[(ks*8 + gc + 4)*FSTR + ni*8 + gr]) };
                mma_tf32(o[ni], pa, b);
            }
        }
    }

    float inv0 = 1.f / l0, inv1 = 1.f / l1;
    const int b = bh / NH_, h = bh % NH_;
    const int srow0 = qt*128 + wid*16 + gr;
    const int pp = (gc < 2) ? 4*gc : 4*gc - 7;
#pragma unroll
    for (int ni = 0; ni < 8; ni++) {
        int colb = h*64 + ni*8;
        float* d0 = g_attn + (size_t)(b*S_ + srow0) * H_ + colb;
        float* d1 = g_attn + (size_t)(b*S_ + srow0 + 8) * H_ + colb;
        // h-permuted store (feeds Wo gemm's K dim)
        d0[pp]   = __uint_as_float(f2tf32(o[ni][0]*inv0));
        d0[pp+2] = __uint_as_float(f2tf32(o[ni][1]*inv0));
        d1[pp]   = __uint_as_float(f2tf32(o[ni][2]*inv1));
        d1[pp+2] = __uint_as_float(f2tf32(o[ni][3]*inv1));
    }
}

// ---------------- launch --------------------------------------------------------------
extern "C" void kernel_launch(void* const* d_in, const int* in_sizes, int n_in,
                              void* d_out, int out_size) {
    (void)in_sizes; (void)n_in; (void)out_size;
    const float* x       = (const float*)d_in[0];
    const float* ve      = (const float*)d_in[1];
    const float* Wqkv    = (const float*)d_in[2];
    const float* Wo      = (const float*)d_in[3];
    const float* lambdas = (const float*)d_in[4];
    float* out = (float*)d_out;

    void *p_qkv, *p_attn, *p_x32, *p_w1, *p_w2;
    cudaGetSymbolAddress(&p_qkv,  g_qkv);
    cudaGetSymbolAddress(&p_attn, g_attn);
    cudaGetSymbolAddress(&p_x32,  g_x32);
    cudaGetSymbolAddress(&p_w1,   g_w1);
    cudaGetSymbolAddress(&p_w2,   g_w2);

    static bool attr_done = false;
    if (!attr_done) {
        cudaFuncSetAttribute(flash_v6, cudaFuncAttributeMaxDynamicSharedMemorySize,
                             FLASH_SMEM_BYTES);
        cudaFuncSetAttribute(gemm_v5, cudaFuncAttributeMaxDynamicSharedMemorySize,
                             GEMM_SMEM_BYTES);
        attr_done = true;
    }

    // 0) tf32-round + k-permute GEMM inputs
    cvt_tf32_perm_kernel<<<ROWS_*H_/8/256, 256>>>(x,    (float*)p_x32, ROWS_*H_);
    cvt_tf32_perm_kernel<<<3*H_*H_/8/256,  256>>>(Wqkv, (float*)p_w1,  3*H_*H_);
    cvt_tf32_perm_kernel<<<H_*H_/8/256,    256>>>(Wo,   (float*)p_w2,  H_*H_);
    // 1) qkv = x @ W_qkv^T
    gemm_v5<<<dim3(3*H_/128, ROWS_/128), 256, GEMM_SMEM_BYTES>>>(
        (const float*)p_x32, (const float*)p_w1, (float*)p_qkv, ROWS_, 3*H_, H_);
    // 2) RoPE table
    rope_table_kernel<<<(S_*32 + 255)/256, 256>>>();
    // 3) prep (writes q/k d-permuted)
    prep_kernel<<<(B_*S_*NH_*32 + 255)/256, 256>>>(ve, lambdas);
    // 4) causal flash attention
    flash_v6<<<dim3(S_/128, B_*NH_), 256, FLASH_SMEM_BYTES>>>();
    // 5) out = attn @ W_o^T
    gemm_v5<<<dim3(H_/128, ROWS_/128), 256, GEMM_SMEM_BYTES>>>(
        (const float*)p_attn, (const float*)p_w2, out, ROWS_, H_, H_);
}

// round 10
// speedup vs baseline: 1.2426x; 1.0232x over previous
#include <cuda_runtime.h>
#include <cuda_bf16.h>
#include <math.h>
#include <stdint.h>

// Problem constants
#define B_  2
#define S_  2048
#define H_  1024
#define NH_ 16
#define D_  64
#define ROWS_ (B_*S_)        // 4096
#define EPS_ 1.1920929e-07f
#define QSCALE_ (0.125f * 1.4426950408889634f)   // (1/sqrt(D)) * log2(e)

// ---------------- scratch -------------------------------------------------------------
__device__ float g_qkv[(size_t)ROWS_ * 3 * H_];   // natural
__device__ float g_q[(size_t)B_*NH_*S_*D_];       // d-permuted (flash frag layout)
__device__ float g_k[(size_t)B_*NH_*S_*D_];       // d-permuted
__device__ float g_v[(size_t)B_*NH_*S_*D_];       // natural
__device__ float g_attn[(size_t)ROWS_ * H_];      // natural, tf32-rounded
__device__ float g_x32[(size_t)ROWS_ * H_];       // tf32 natural
__device__ float g_w1[(size_t)3*H_ * H_];         // tf32 natural
__device__ float g_w2[(size_t)H_ * H_];           // tf32 natural
__device__ float g_cos[S_*32];
__device__ float g_sin[S_*32];

// ---------------- helpers -------------------------------------------------------------
__device__ __forceinline__ unsigned f2tf32(float f) {
    unsigned u;
    asm("cvt.rna.tf32.f32 %0, %1;" : "=r"(u) : "f"(f));
    return u;
}
__device__ __forceinline__ float ex2(float x) {
    float r;
    asm("ex2.approx.f32 %0, %1;" : "=f"(r) : "f"(x));
    return r;
}
__device__ __forceinline__ void mma_tf32(float c[4], const unsigned a[4], const unsigned b[2]) {
    asm volatile(
        "mma.sync.aligned.m16n8k8.row.col.f32.tf32.tf32.f32 "
        "{%0,%1,%2,%3}, {%4,%5,%6,%7}, {%8,%9}, {%0,%1,%2,%3};"
        : "+f"(c[0]), "+f"(c[1]), "+f"(c[2]), "+f"(c[3])
        : "r"(a[0]), "r"(a[1]), "r"(a[2]), "r"(a[3]), "r"(b[0]), "r"(b[1]));
}
__device__ __forceinline__ void cp16(unsigned dst, const void* src) {
    asm volatile("cp.async.cg.shared.global [%0], [%1], 16;" :: "r"(dst), "l"(src));
}
__device__ __forceinline__ uint32_t smem_u32(const void* p) {
    return (uint32_t)__cvta_generic_to_shared(p);
}

// ---------------- elementwise tf32 rounding (natural layout) --------------------------
__global__ void cvt_tf32_kernel(const float* __restrict__ in, float* __restrict__ out, int n) {
    int i = (blockIdx.x * blockDim.x + threadIdx.x) * 4;
    if (i >= n) return;
    float4 v = *(const float4*)(in + i);
    float4 o;
    o.x = __uint_as_float(f2tf32(v.x));
    o.y = __uint_as_float(f2tf32(v.y));
    o.z = __uint_as_float(f2tf32(v.z));
    o.w = __uint_as_float(f2tf32(v.w));
    *(float4*)(out + i) = o;
}

// ---------------- RoPE table ----------------------------------------------------------
__global__ void rope_table_kernel() {
    int idx = blockIdx.x * blockDim.x + threadIdx.x;
    if (idx >= S_*32) return;
    int s = idx >> 5, j = idx & 31;
    double invf = pow(1.0e-4, (double)j / 32.0);
    float f = (float)s * (float)invf;
    double sn, cs;
    sincos((double)f, &sn, &cs);
    g_cos[idx] = (float)cs;
    g_sin[idx] = (float)sn;
}

// ---------------- tf32 GEMM v6: gemm_v4 body + 3 cp.async stages ----------------------
// C[M,N] = A[M,K] * B[N,K]^T. Inputs tf32-pre-rounded, natural layout.
// 128x128 tile, BK=32, pad-36 rows, scalar frag LDS (base+imm addressing), 3 stages.
#define GP 36
#define GSLAB (128*GP)                         // words per matrix per stage
#define GEMM_SMEM_BYTES (6*GSLAB*4)            // 110592 -> 2 CTAs/SM

__global__ __launch_bounds__(256, 2)
void gemm_v6(const float* __restrict__ A, const float* __restrict__ Bm,
             float* __restrict__ C, int M, int N, int K) {
    extern __shared__ unsigned smg[];
    unsigned* As = smg;                        // [3][128][GP]
    unsigned* Bs = smg + 3*GSLAB;

    const int tid  = threadIdx.x;
    const int lane = tid & 31;
    const int wid  = tid >> 5;
    const int gr   = lane >> 2;
    const int gc   = lane & 3;
    const int bm = blockIdx.y * 128;
    const int bn = blockIdx.x * 128;
    const int wm = (wid >> 1) * 32;
    const int wn = (wid & 1) * 64;

    const int lr = tid >> 2;                   // 0..63
    const int lc = (tid & 3) << 2;             // 0,4,8,12
    const unsigned as_u32 = smem_u32(As);
    const unsigned bs_u32 = smem_u32(Bs);

    auto load_slab = [&](int t, int s) {
        const int k0 = t << 5;
        const unsigned ad = as_u32 + (unsigned)(s*GSLAB*4);
        const unsigned bd = bs_u32 + (unsigned)(s*GSLAB*4);
#pragma unroll
        for (int rr = 0; rr < 2; rr++) {
            int r = lr + rr*64;
#pragma unroll
            for (int cc = 0; cc < 2; cc++) {
                int c = lc + cc*16;
                unsigned off = (unsigned)((r*GP + c) * 4);
                cp16(ad + off, A  + (size_t)(bm + r) * K + k0 + c);
                cp16(bd + off, Bm + (size_t)(bn + r) * K + k0 + c);
            }
        }
        asm volatile("cp.async.commit_group;");
    };

    float acc[2][8][4];
#pragma unroll
    for (int mi = 0; mi < 2; mi++)
#pragma unroll
        for (int ni = 0; ni < 8; ni++)
#pragma unroll
            for (int j = 0; j < 4; j++) acc[mi][ni][j] = 0.f;

    const int T = K >> 5;                      // 32 slabs
    load_slab(0, 0);
    if (T > 1) load_slab(1, 1);

    for (int t = 0; t < T; t++) {
        const int cur = t % 3;
        __syncthreads();                       // stage (t-1)%3 reads done -> reusable
        if (t + 2 < T) {
            load_slab(t + 2, (t + 2) % 3);
            asm volatile("cp.async.wait_group 2;");
        } else if (t + 1 < T) {
            asm volatile("cp.async.wait_group 1;");
        } else {
            asm volatile("cp.async.wait_group 0;");
        }
        __syncthreads();                       // stage cur visible

        const unsigned* Ab = As + cur*GSLAB;
        const unsigned* Bb = Bs + cur*GSLAB;
#pragma unroll
        for (int ks = 0; ks < 4; ks++) {
            const int kb = ks * 8;
            unsigned a[2][4];
#pragma unroll
            for (int mi = 0; mi < 2; mi++) {
                const unsigned* ap = &Ab[(wm + mi*16 + gr)*GP + kb + gc];
                a[mi][0] = ap[0];
                a[mi][1] = ap[8*GP];
                a[mi][2] = ap[4];
                a[mi][3] = ap[8*GP + 4];
            }
#pragma unroll
            for (int ni = 0; ni < 8; ni++) {
                const unsigned* bp = &Bb[(wn + ni*8 + gr)*GP + kb + gc];
                unsigned b[2] = { bp[0], bp[4] };
                mma_tf32(acc[0][ni], a[0], b);
                mma_tf32(acc[1][ni], a[1], b);
            }
        }
    }

#pragma unroll
    for (int mi = 0; mi < 2; mi++) {
        int m0 = bm + wm + mi*16 + gr;
#pragma unroll
        for (int ni = 0; ni < 8; ni++) {
            int n = bn + wn + ni*8 + 2*gc;
            *(float2*)(C + (size_t)m0 * N + n)       = make_float2(acc[mi][ni][0], acc[mi][ni][1]);
            *(float2*)(C + (size_t)(m0 + 8) * N + n) = make_float2(acc[mi][ni][2], acc[mi][ni][3]);
        }
    }
}

// ---------------- prep: RMSNorm+RoPE, lambda-mix; q/k stored d-permuted ---------------
__global__ void prep_kernel(const float* __restrict__ ve, const float* __restrict__ lambdas) {
    int gtid = blockIdx.x * blockDim.x + threadIdx.x;
    int warp = gtid >> 5;
    int lane = gtid & 31;
    if (warp >= B_*S_*NH_) return;
    int h = warp % NH_;
    int s = (warp / NH_) % S_;
    int b = warp / (NH_ * S_);

    const float* row = g_qkv + (size_t)(b*S_ + s) * (3*H_);
    float q1 = row[h*64 + lane],          q2 = row[h*64 + 32 + lane];
    float k1 = row[H_ + h*64 + lane],     k2 = row[H_ + h*64 + 32 + lane];
    float v1 = row[2*H_ + h*64 + lane],   v2 = row[2*H_ + h*64 + 32 + lane];

    float sq = q1*q1 + q2*q2;
    float sk = k1*k1 + k2*k2;
#pragma unroll
    for (int o = 16; o; o >>= 1) {
        sq += __shfl_xor_sync(0xffffffffu, sq, o);
        sk += __shfl_xor_sync(0xffffffffu, sk, o);
    }
    float rq = rsqrtf(sq * (1.f/64.f) + EPS_);
    float rk = rsqrtf(sk * (1.f/64.f) + EPS_);
    q1 *= rq; q2 *= rq; k1 *= rk; k2 *= rk;

    float c  = g_cos[s*32 + lane];
    float sn = g_sin[s*32 + lane];
    float qo1 = (q1*c + q2*sn) * QSCALE_;
    float qo2 = (q2*c - q1*sn) * QSCALE_;
    float ko1 = k1*c + k2*sn, ko2 = k2*c - k1*sn;

    float l0 = lambdas[0], l1 = lambdas[1];
    const float* verow = ve + (size_t)(b*S_ + s) * H_ + h*64;
    float vo1 = l0*v1 + l1*verow[lane];
    float vo2 = l0*v2 + l1*verow[32 + lane];

    size_t ob = ((size_t)(b*NH_ + h) * S_ + s) * 64;
    // permuted positions within each 8-group: k -> 2*(k&3) + (k>>2 & 1)
    int j    = lane & 7;
    int pbase = (lane >> 3) * 8 + 2*(j & 3) + (j >> 2);
    g_q[ob + pbase]      = __uint_as_float(f2tf32(qo1));
    g_q[ob + pbase + 32] = __uint_as_float(f2tf32(qo2));
    g_k[ob + pbase]      = __uint_as_float(f2tf32(ko1));
    g_k[ob + pbase + 32] = __uint_as_float(f2tf32(ko2));
    g_v[ob + lane]       = __uint_as_float(f2tf32(vo1));   // V natural
    g_v[ob + lane + 32]  = __uint_as_float(f2tf32(vo2));
}

// ---------------- flash attention v6 (R9 winner; natural output store) ----------------
#define FSTR 72
#define STAGE_W (64*FSTR)
#define FLASH_SMEM_BYTES ((128*FSTR + 4*STAGE_W)*4)   // 110592

__global__ __launch_bounds__(256, 2)
void flash_v6() {
    extern __shared__ float sm[];
    float* QP = sm;                    // 128 x 72 (Q d-permuted; later P n-permuted)
    float* Ks = sm + 128*FSTR;         // 2 x 64 x 72 (d-permuted)
    float* Vs = Ks + 2*STAGE_W;        // 2 x 64 x 72 (natural)

    const int tid  = threadIdx.x;
    const int lane = tid & 31;
    const int wid  = tid >> 5;
    const int gr   = lane >> 2;
    const int gc   = lane & 3;
    const int qt   = gridDim.x - 1 - blockIdx.x;
    const int bh   = blockIdx.y;
    const int arow = wid*16 + gr;

    const unsigned ks_u32 = smem_u32(Ks);
    const unsigned vs_u32 = smem_u32(Vs);
    const float* Kbase = g_k + (size_t)bh * S_ * 64;
    const float* Vbase = g_v + (size_t)bh * S_ * 64;
    const int ktmax = 2*qt + 1;

    const int cr = tid >> 4;
    const int cc = (tid & 15) << 2;

    {
#pragma unroll
        for (int j = 0; j < 4; j++) {
            int r = cr + j*16;
            unsigned off = (unsigned)((r*FSTR + cc) * 4);
            cp16(ks_u32 + off, Kbase + r*64 + cc);
            cp16(vs_u32 + off, Vbase + r*64 + cc);
        }
        asm volatile("cp.async.commit_group;");
    }

    const float* Qg = g_q + ((size_t)bh * S_ + qt*128) * 64;
    for (int i = tid; i < 2048; i += 256) {
        int r = i >> 4, dc = (i & 15) << 2;
        *(float4*)&QP[r*FSTR + dc] = *(const float4*)(Qg + r*64 + dc);
    }
    __syncthreads();

    unsigned qa[8][4];
#pragma unroll
    for (int ks = 0; ks < 8; ks++) {
        uint2 lo = *(const uint2*)&QP[arow*FSTR + ks*8 + 2*gc];
        uint2 hi = *(const uint2*)&QP[(arow+8)*FSTR + ks*8 + 2*gc];
        qa[ks][0] = lo.x; qa[ks][1] = hi.x; qa[ks][2] = lo.y; qa[ks][3] = hi.y;
    }

    float o[8][4];
#pragma unroll
    for (int ni = 0; ni < 8; ni++)
#pragma unroll
        for (int j = 0; j < 4; j++) o[ni][j] = 0.f;
    float m0 = -INFINITY, m1 = -INFINITY, l0 = 0.f, l1 = 0.f;

    for (int kt = 0; kt <= ktmax; kt++) {
        const int cur = kt & 1;
        __syncthreads();

        if (kt < ktmax) {
            const int nst = cur ^ 1;
            const float* Kg = Kbase + (size_t)(kt+1)*64*64;
            const float* Vg = Vbase + (size_t)(kt+1)*64*64;
            unsigned kd = ks_u32 + (unsigned)(nst*STAGE_W*4);
            unsigned vd = vs_u32 + (unsigned)(nst*STAGE_W*4);
#pragma unroll
            for (int j = 0; j < 4; j++) {
                int r = cr + j*16;
                unsigned off = (unsigned)((r*FSTR + cc) * 4);
                cp16(kd + off, Kg + r*64 + cc);
                cp16(vd + off, Vg + r*64 + cc);
            }
            asm volatile("cp.async.commit_group;");
            asm volatile("cp.async.wait_group 1;");
        } else {
            asm volatile("cp.async.wait_group 0;");
        }
        __syncthreads();

        const float* Kst = Ks + cur*STAGE_W;
        const float* Vst = Vs + cur*STAGE_W;

        // S = Q K^T  (uint2 b-frags from permuted K)
        float sc[8][4];
#pragma unroll
        for (int ni = 0; ni < 8; ni++)
#pragma unroll
            for (int j = 0; j < 4; j++) sc[ni][j] = 0.f;
#pragma unroll
        for (int ks = 0; ks < 8; ks++) {
#pragma unroll
            for (int ni = 0; ni < 8; ni++) {
                uint2 bb = *(const uint2*)&Kst[(ni*8 + gr)*FSTR + ks*8 + 2*gc];
                unsigned b[2] = { bb.x, bb.y };
                mma_tf32(sc[ni], qa[ks], b);
            }
        }

        const int qrow0 = qt*128 + wid*16 + gr;
        if (kt >= 2*qt) {
#pragma unroll
            for (int ni = 0; ni < 8; ni++) {
                int col = kt*64 + ni*8 + 2*gc;
                if (col     > qrow0)     sc[ni][0] = -1e30f;
                if (col + 1 > qrow0)     sc[ni][1] = -1e30f;
                if (col     > qrow0 + 8) sc[ni][2] = -1e30f;
                if (col + 1 > qrow0 + 8) sc[ni][3] = -1e30f;
            }
        }

        float mx0 = -INFINITY, mx1 = -INFINITY;
#pragma unroll
        for (int ni = 0; ni < 8; ni++) {
            mx0 = fmaxf(mx0, fmaxf(sc[ni][0], sc[ni][1]));
            mx1 = fmaxf(mx1, fmaxf(sc[ni][2], sc[ni][3]));
        }
        mx0 = fmaxf(mx0, __shfl_xor_sync(0xffffffffu, mx0, 1));
        mx0 = fmaxf(mx0, __shfl_xor_sync(0xffffffffu, mx0, 2));
        mx1 = fmaxf(mx1, __shfl_xor_sync(0xffffffffu, mx1, 1));
        mx1 = fmaxf(mx1, __shfl_xor_sync(0xffffffffu, mx1, 2));
        float mn0 = fmaxf(m0, mx0), mn1 = fmaxf(m1, mx1);
        float al0 = ex2(m0 - mn0), al1 = ex2(m1 - mn1);
        m0 = mn0; m1 = mn1;

        // P stored n-permuted: cols (pp, pp+2) within the ni-group
        const int pp = (gc < 2) ? 4*gc : 4*gc - 7;
        float* pr0 = &QP[arow*FSTR];
        float* pr1 = &QP[(arow+8)*FSTR];
        float s0 = 0.f, s1 = 0.f;
#pragma unroll
        for (int ni = 0; ni < 8; ni++) {
            float p00 = ex2(sc[ni][0] - mn0);
            float p01 = ex2(sc[ni][1] - mn0);
            float p10 = ex2(sc[ni][2] - mn1);
            float p11 = ex2(sc[ni][3] - mn1);
            s0 += p00 + p01;
            s1 += p10 + p11;
            int c = ni*8 + pp;
            pr0[c]   = p00;  pr0[c+2] = p01;
            pr1[c]   = p10;  pr1[c+2] = p11;
        }
        s0 += __shfl_xor_sync(0xffffffffu, s0, 1);
        s0 += __shfl_xor_sync(0xffffffffu, s0, 2);
        s1 += __shfl_xor_sync(0xffffffffu, s1, 1);
        s1 += __shfl_xor_sync(0xffffffffu, s1, 2);
        l0 = l0 * al0 + s0;
        l1 = l1 * al1 + s1;

#pragma unroll
        for (int ni = 0; ni < 8; ni++) {
            o[ni][0] *= al0; o[ni][1] *= al0;
            o[ni][2] *= al1; o[ni][3] *= al1;
        }
        __syncwarp();

        // O += P V  (uint2 a-frags from permuted P; scalar V b-frags)
#pragma unroll
        for (int ks = 0; ks < 8; ks++) {
            uint2 plo = *(const uint2*)&QP[arow*FSTR + ks*8 + 2*gc];
            uint2 phi = *(const uint2*)&QP[(arow+8)*FSTR + ks*8 + 2*gc];
            unsigned pa[4] = { plo.x, phi.x, plo.y, phi.y };
#pragma unroll
            for (int ni = 0; ni < 8; ni++) {
                unsigned b[2] = { __float_as_uint(Vst[(ks*8 + gc)*FSTR + ni*8 + gr]),
                                  __float_as_uint(Vst[(ks*8 + gc + 4)*FSTR + ni*8 + gr]) };
                mma_tf32(o[ni], pa, b);
            }
        }
    }

    float inv0 = 1.f / l0, inv1 = 1.f / l1;
    const int b = bh / NH_, h = bh % NH_;
    const int srow0 = qt*128 + wid*16 + gr;
#pragma unroll
    for (int ni = 0; ni < 8; ni++) {
        int col = h*64 + ni*8 + 2*gc;
        // natural layout, tf32-rounded (feeds natural-layout Wo gemm via cp.async)
        *(float2*)(g_attn + (size_t)(b*S_ + srow0) * H_ + col) =
            make_float2(__uint_as_float(f2tf32(o[ni][0]*inv0)),
                        __uint_as_float(f2tf32(o[ni][1]*inv0)));
        *(float2*)(g_attn + (size_t)(b*S_ + srow0 + 8) * H_ + col) =
            make_float2(__uint_as_float(f2tf32(o[ni][2]*inv1)),
                        __uint_as_float(f2tf32(o[ni][3]*inv1)));
    }
}

// ---------------- launch --------------------------------------------------------------
extern "C" void kernel_launch(void* const* d_in, const int* in_sizes, int n_in,
                              void* d_out, int out_size) {
    (void)in_sizes; (void)n_in; (void)out_size;
    const float* x       = (const float*)d_in[0];
    const float* ve      = (const float*)d_in[1];
    const float* Wqkv    = (const float*)d_in[2];
    const float* Wo      = (const float*)d_in[3];
    const float* lambdas = (const float*)d_in[4];
    float* out = (float*)d_out;

    void *p_qkv, *p_attn, *p_x32, *p_w1, *p_w2;
    cudaGetSymbolAddress(&p_qkv,  g_qkv);
    cudaGetSymbolAddress(&p_attn, g_attn);
    cudaGetSymbolAddress(&p_x32,  g_x32);
    cudaGetSymbolAddress(&p_w1,   g_w1);
    cudaGetSymbolAddress(&p_w2,   g_w2);

    static bool attr_done = false;
    if (!attr_done) {
        cudaFuncSetAttribute(flash_v6, cudaFuncAttributeMaxDynamicSharedMemorySize,
                             FLASH_SMEM_BYTES);
        cudaFuncSetAttribute(gemm_v6, cudaFuncAttributeMaxDynamicSharedMemorySize,
                             GEMM_SMEM_BYTES);
        attr_done = true;
    }

    // 0) tf32-pre-round GEMM inputs (natural layout)
    cvt_tf32_kernel<<<ROWS_*H_/4/256, 256>>>(x,    (float*)p_x32, ROWS_*H_);
    cvt_tf32_kernel<<<3*H_*H_/4/256,  256>>>(Wqkv, (float*)p_w1,  3*H_*H_);
    cvt_tf32_kernel<<<H_*H_/4/256,    256>>>(Wo,   (float*)p_w2,  H_*H_);
    // 1) qkv = x @ W_qkv^T
    gemm_v6<<<dim3(3*H_/128, ROWS_/128), 256, GEMM_SMEM_BYTES>>>(
        (const float*)p_x32, (const float*)p_w1, (float*)p_qkv, ROWS_, 3*H_, H_);
    // 2) RoPE table
    rope_table_kernel<<<(S_*32 + 255)/256, 256>>>();
    // 3) prep (writes q/k d-permuted for flash)
    prep_kernel<<<(B_*S_*NH_*32 + 255)/256, 256>>>(ve, lambdas);
    // 4) causal flash attention
    flash_v6<<<dim3(S_/128, B_*NH_), 256, FLASH_SMEM_BYTES>>>();
    // 5) out = attn @ W_o^T
    gemm_v6<<<dim3(H_/128, ROWS_/128), 256, GEMM_SMEM_BYTES>>>(
        (const float*)p_attn, (const float*)p_w2, out, ROWS_, H_, H_);
}

// round 12
// speedup vs baseline: 1.3551x; 1.0905x over previous
#include <cuda_runtime.h>
#include <cuda_bf16.h>
#include <math.h>
#include <stdint.h>

// Problem constants
#define B_  2
#define S_  2048
#define H_  1024
#define NH_ 16
#define D_  64
#define ROWS_ (B_*S_)        // 4096
#define EPS_ 1.1920929e-07f
#define QSCALE_ (0.125f * 1.4426950408889634f)   // (1/sqrt(D)) * log2(e)

// ---------------- scratch -------------------------------------------------------------
__device__ float g_qkv[(size_t)ROWS_ * 3 * H_];   // natural
__device__ float g_q[(size_t)B_*NH_*S_*D_];       // d-permuted (flash frag layout)
__device__ float g_k[(size_t)B_*NH_*S_*D_];       // d-permuted
__device__ float g_v[(size_t)B_*NH_*S_*D_];       // natural
__device__ float g_attn[(size_t)ROWS_ * H_];      // natural, tf32-rounded
__device__ float g_x32[(size_t)ROWS_ * H_];       // tf32 natural
__device__ float g_w1[(size_t)3*H_ * H_];         // tf32 natural
__device__ float g_w2[(size_t)H_ * H_];           // tf32 natural
__device__ float g_cos[S_*32];
__device__ float g_sin[S_*32];

// ---------------- helpers -------------------------------------------------------------
__device__ __forceinline__ unsigned f2tf32(float f) {
    unsigned u;
    asm("cvt.rna.tf32.f32 %0, %1;" : "=r"(u) : "f"(f));
    return u;
}
__device__ __forceinline__ float ex2(float x) {
    float r;
    asm("ex2.approx.f32 %0, %1;" : "=f"(r) : "f"(x));
    return r;
}
__device__ __forceinline__ void mma_tf32(float c[4], const unsigned a[4], const unsigned b[2]) {
    asm volatile(
        "mma.sync.aligned.m16n8k8.row.col.f32.tf32.tf32.f32 "
        "{%0,%1,%2,%3}, {%4,%5,%6,%7}, {%8,%9}, {%0,%1,%2,%3};"
        : "+f"(c[0]), "+f"(c[1]), "+f"(c[2]), "+f"(c[3])
        : "r"(a[0]), "r"(a[1]), "r"(a[2]), "r"(a[3]), "r"(b[0]), "r"(b[1]));
}
__device__ __forceinline__ void cp16(unsigned dst, const void* src) {
    asm volatile("cp.async.cg.shared.global [%0], [%1], 16;" :: "r"(dst), "l"(src));
}
__device__ __forceinline__ uint32_t smem_u32(const void* p) {
    return (uint32_t)__cvta_generic_to_shared(p);
}

// ---------------- elementwise tf32 rounding (natural layout) --------------------------
__global__ void cvt_tf32_kernel(const float* __restrict__ in, float* __restrict__ out, int n) {
    int i = (blockIdx.x * blockDim.x + threadIdx.x) * 4;
    if (i >= n) return;
    float4 v = *(const float4*)(in + i);
    float4 o;
    o.x = __uint_as_float(f2tf32(v.x));
    o.y = __uint_as_float(f2tf32(v.y));
    o.z = __uint_as_float(f2tf32(v.z));
    o.w = __uint_as_float(f2tf32(v.w));
    *(float4*)(out + i) = o;
}

// ---------------- RoPE table ----------------------------------------------------------
__global__ void rope_table_kernel() {
    int idx = blockIdx.x * blockDim.x + threadIdx.x;
    if (idx >= S_*32) return;
    int s = idx >> 5, j = idx & 31;
    double invf = pow(1.0e-4, (double)j / 32.0);
    float f = (float)s * (float)invf;
    double sn, cs;
    sincos((double)f, &sn, &cs);
    g_cos[idx] = (float)cs;
    g_sin[idx] = (float)sn;
}

// ---------------- tf32 GEMM v8: 3 stages, ONE sync per slab (wait BEFORE barrier) -----
// Per slab t: issue load(t+1) into stage (t+1)%3, cp.async.wait_group 1 (slab t done),
// __syncthreads (publishes ALL warps' slab-t copies), compute stage t%3.
// Laggard warps (still in compute t-1) read stage (t-1)%3 != (t+1)%3 -> no WAR hazard.
// C[M,N] = A[M,K] * B[N,K]^T, inputs tf32-pre-rounded natural layout.
#define GP 36
#define GSLAB (128*GP)
#define GEMM_SMEM_BYTES (6*GSLAB*4)            // 110592 -> 2 CTAs/SM

__global__ __launch_bounds__(256, 2)
void gemm_v8(const float* __restrict__ A, const float* __restrict__ Bm,
             float* __restrict__ C, int M, int N, int K) {
    extern __shared__ unsigned smg[];
    unsigned* As = smg;                        // [3][128][GP]
    unsigned* Bs = smg + 3*GSLAB;

    const int tid  = threadIdx.x;
    const int lane = tid & 31;
    const int wid  = tid >> 5;
    const int gr   = lane >> 2;
    const int gc   = lane & 3;
    const int bm = blockIdx.y * 128;
    const int bn = blockIdx.x * 128;
    const int wm = (wid >> 1) * 32;
    const int wn = (wid & 1) * 64;

    const int lr = tid >> 2;                   // 0..63
    const int lc = (tid & 3) << 2;             // 0,4,8,12
    const unsigned as_u32 = smem_u32(As);
    const unsigned bs_u32 = smem_u32(Bs);

    auto load_slab = [&](int t, int s) {
        const int k0 = t << 5;
        const unsigned ad = as_u32 + (unsigned)(s*GSLAB*4);
        const unsigned bd = bs_u32 + (unsigned)(s*GSLAB*4);
#pragma unroll
        for (int rr = 0; rr < 2; rr++) {
            int r = lr + rr*64;
#pragma unroll
            for (int cc = 0; cc < 2; cc++) {
                int c = lc + cc*16;
                unsigned off = (unsigned)((r*GP + c) * 4);
                cp16(ad + off, A  + (size_t)(bm + r) * K + k0 + c);
                cp16(bd + off, Bm + (size_t)(bn + r) * K + k0 + c);
            }
        }
        asm volatile("cp.async.commit_group;");
    };

    float acc[2][8][4];
#pragma unroll
    for (int mi = 0; mi < 2; mi++)
#pragma unroll
        for (int ni = 0; ni < 8; ni++)
#pragma unroll
            for (int j = 0; j < 4; j++) acc[mi][ni][j] = 0.f;

    const int T = K >> 5;                      // 32 slabs
    load_slab(0, 0);

    for (int t = 0; t < T; t++) {
        const int cur = t % 3;
        if (t + 1 < T) {
            load_slab(t + 1, (t + 1) % 3);     // prefetch while others may still compute t-1
            asm volatile("cp.async.wait_group 1;");   // THIS warp's slab-t copies done
        } else {
            asm volatile("cp.async.wait_group 0;");
        }
        __syncthreads();                       // all warps waited -> slab t visible to all

        const unsigned* Ab = As + cur*GSLAB;
        const unsigned* Bb = Bs + cur*GSLAB;
#pragma unroll
        for (int ks = 0; ks < 4; ks++) {
            const int kb = ks * 8;
            unsigned a[2][4];
#pragma unroll
            for (int mi = 0; mi < 2; mi++) {
                const unsigned* ap = &Ab[(wm + mi*16 + gr)*GP + kb + gc];
                a[mi][0] = ap[0];
                a[mi][1] = ap[8*GP];
                a[mi][2] = ap[4];
                a[mi][3] = ap[8*GP + 4];
            }
#pragma unroll
            for (int ni = 0; ni < 8; ni++) {
                const unsigned* bp = &Bb[(wn + ni*8 + gr)*GP + kb + gc];
                unsigned b[2] = { bp[0], bp[4] };
                mma_tf32(acc[0][ni], a[0], b);
                mma_tf32(acc[1][ni], a[1], b);
            }
        }
    }

#pragma unroll
    for (int mi = 0; mi < 2; mi++) {
        int m0 = bm + wm + mi*16 + gr;
#pragma unroll
        for (int ni = 0; ni < 8; ni++) {
            int n = bn + wn + ni*8 + 2*gc;
            *(float2*)(C + (size_t)m0 * N + n)       = make_float2(acc[mi][ni][0], acc[mi][ni][1]);
            *(float2*)(C + (size_t)(m0 + 8) * N + n) = make_float2(acc[mi][ni][2], acc[mi][ni][3]);
        }
    }
}

// ---------------- prep: RMSNorm+RoPE, lambda-mix; q/k stored d-permuted ---------------
__global__ void prep_kernel(const float* __restrict__ ve, const float* __restrict__ lambdas) {
    int gtid = blockIdx.x * blockDim.x + threadIdx.x;
    int warp = gtid >> 5;
    int lane = gtid & 31;
    if (warp >= B_*S_*NH_) return;
    int h = warp % NH_;
    int s = (warp / NH_) % S_;
    int b = warp / (NH_ * S_);

    const float* row = g_qkv + (size_t)(b*S_ + s) * (3*H_);
    float q1 = row[h*64 + lane],          q2 = row[h*64 + 32 + lane];
    float k1 = row[H_ + h*64 + lane],     k2 = row[H_ + h*64 + 32 + lane];
    float v1 = row[2*H_ + h*64 + lane],   v2 = row[2*H_ + h*64 + 32 + lane];

    float sq = q1*q1 + q2*q2;
    float sk = k1*k1 + k2*k2;
#pragma unroll
    for (int o = 16; o; o >>= 1) {
        sq += __shfl_xor_sync(0xffffffffu, sq, o);
        sk += __shfl_xor_sync(0xffffffffu, sk, o);
    }
    float rq = rsqrtf(sq * (1.f/64.f) + EPS_);
    float rk = rsqrtf(sk * (1.f/64.f) + EPS_);
    q1 *= rq; q2 *= rq; k1 *= rk; k2 *= rk;

    float c  = g_cos[s*32 + lane];
    float sn = g_sin[s*32 + lane];
    float qo1 = (q1*c + q2*sn) * QSCALE_;
    float qo2 = (q2*c - q1*sn) * QSCALE_;
    float ko1 = k1*c + k2*sn, ko2 = k2*c - k1*sn;

    float l0 = lambdas[0], l1 = lambdas[1];
    const float* verow = ve + (size_t)(b*S_ + s) * H_ + h*64;
    float vo1 = l0*v1 + l1*verow[lane];
    float vo2 = l0*v2 + l1*verow[32 + lane];

    size_t ob = ((size_t)(b*NH_ + h) * S_ + s) * 64;
    int j    = lane & 7;
    int pbase = (lane >> 3) * 8 + 2*(j & 3) + (j >> 2);
    g_q[ob + pbase]      = __uint_as_float(f2tf32(qo1));
    g_q[ob + pbase + 32] = __uint_as_float(f2tf32(qo2));
    g_k[ob + pbase]      = __uint_as_float(f2tf32(ko1));
    g_k[ob + pbase + 32] = __uint_as_float(f2tf32(ko2));
    g_v[ob + lane]       = __uint_as_float(f2tf32(vo1));
    g_v[ob + lane + 32]  = __uint_as_float(f2tf32(vo2));
}

// ---------------- flash attention v6 (unchanged R10 winner) ---------------------------
#define FSTR 72
#define STAGE_W (64*FSTR)
#define FLASH_SMEM_BYTES ((128*FSTR + 4*STAGE_W)*4)   // 110592

__global__ __launch_bounds__(256, 2)
void flash_v6() {
    extern __shared__ float sm[];
    float* QP = sm;
    float* Ks = sm + 128*FSTR;
    float* Vs = Ks + 2*STAGE_W;

    const int tid  = threadIdx.x;
    const int lane = tid & 31;
    const int wid  = tid >> 5;
    const int gr   = lane >> 2;
    const int gc   = lane & 3;
    const int qt   = gridDim.x - 1 - blockIdx.x;
    const int bh   = blockIdx.y;
    const int arow = wid*16 + gr;

    const unsigned ks_u32 = smem_u32(Ks);
    const unsigned vs_u32 = smem_u32(Vs);
    const float* Kbase = g_k + (size_t)bh * S_ * 64;
    const float* Vbase = g_v + (size_t)bh * S_ * 64;
    const int ktmax = 2*qt + 1;

    const int cr = tid >> 4;
    const int cc = (tid & 15) << 2;

    {
#pragma unroll
        for (int j = 0; j < 4; j++) {
            int r = cr + j*16;
            unsigned off = (unsigned)((r*FSTR + cc) * 4);
            cp16(ks_u32 + off, Kbase + r*64 + cc);
            cp16(vs_u32 + off, Vbase + r*64 + cc);
        }
        asm volatile("cp.async.commit_group;");
    }

    const float* Qg = g_q + ((size_t)bh * S_ + qt*128) * 64;
    for (int i = tid; i < 2048; i += 256) {
        int r = i >> 4, dc = (i & 15) << 2;
        *(float4*)&QP[r*FSTR + dc] = *(const float4*)(Qg + r*64 + dc);
    }
    __syncthreads();

    unsigned qa[8][4];
#pragma unroll
    for (int ks = 0; ks < 8; ks++) {
        uint2 lo = *(const uint2*)&QP[arow*FSTR + ks*8 + 2*gc];
        uint2 hi = *(const uint2*)&QP[(arow+8)*FSTR + ks*8 + 2*gc];
        qa[ks][0] = lo.x; qa[ks][1] = hi.x; qa[ks][2] = lo.y; qa[ks][3] = hi.y;
    }

    float o[8][4];
#pragma unroll
    for (int ni = 0; ni < 8; ni++)
#pragma unroll
        for (int j = 0; j < 4; j++) o[ni][j] = 0.f;
    float m0 = -INFINITY, m1 = -INFINITY, l0 = 0.f, l1 = 0.f;

    for (int kt = 0; kt <= ktmax; kt++) {
        const int cur = kt & 1;
        __syncthreads();

        if (kt < ktmax) {
            const int nst = cur ^ 1;
            const float* Kg = Kbase + (size_t)(kt+1)*64*64;
            const float* Vg = Vbase + (size_t)(kt+1)*64*64;
            unsigned kd = ks_u32 + (unsigned)(nst*STAGE_W*4);
            unsigned vd = vs_u32 + (unsigned)(nst*STAGE_W*4);
#pragma unroll
            for (int j = 0; j < 4; j++) {
                int r = cr + j*16;
                unsigned off = (unsigned)((r*FSTR + cc) * 4);
                cp16(kd + off, Kg + r*64 + cc);
                cp16(vd + off, Vg + r*64 + cc);
            }
            asm volatile("cp.async.commit_group;");
            asm volatile("cp.async.wait_group 1;");
        } else {
            asm volatile("cp.async.wait_group 0;");
        }
        __syncthreads();

        const float* Kst = Ks + cur*STAGE_W;
        const float* Vst = Vs + cur*STAGE_W;

        float sc[8][4];
#pragma unroll
        for (int ni = 0; ni < 8; ni++)
#pragma unroll
            for (int j = 0; j < 4; j++) sc[ni][j] = 0.f;
#pragma unroll
        for (int ks = 0; ks < 8; ks++) {
#pragma unroll
            for (int ni = 0; ni < 8; ni++) {
                uint2 bb = *(const uint2*)&Kst[(ni*8 + gr)*FSTR + ks*8 + 2*gc];
                unsigned b[2] = { bb.x, bb.y };
                mma_tf32(sc[ni], qa[ks], b);
            }
        }

        const int qrow0 = qt*128 + wid*16 + gr;
        if (kt >= 2*qt) {
#pragma unroll
            for (int ni = 0; ni < 8; ni++) {
                int col = kt*64 + ni*8 + 2*gc;
                if (col     > qrow0)     sc[ni][0] = -1e30f;
                if (col + 1 > qrow0)     sc[ni][1] = -1e30f;
                if (col     > qrow0 + 8) sc[ni][2] = -1e30f;
                if (col + 1 > qrow0 + 8) sc[ni][3] = -1e30f;
            }
        }

        float mx0 = -INFINITY, mx1 = -INFINITY;
#pragma unroll
        for (int ni = 0; ni < 8; ni++) {
            mx0 = fmaxf(mx0, fmaxf(sc[ni][0], sc[ni][1]));
            mx1 = fmaxf(mx1, fmaxf(sc[ni][2], sc[ni][3]));
        }
        mx0 = fmaxf(mx0, __shfl_xor_sync(0xffffffffu, mx0, 1));
        mx0 = fmaxf(mx0, __shfl_xor_sync(0xffffffffu, mx0, 2));
        mx1 = fmaxf(mx1, __shfl_xor_sync(0xffffffffu, mx1, 1));
        mx1 = fmaxf(mx1, __shfl_xor_sync(0xffffffffu, mx1, 2));
        float mn0 = fmaxf(m0, mx0), mn1 = fmaxf(m1, mx1);
        float al0 = ex2(m0 - mn0), al1 = ex2(m1 - mn1);
        m0 = mn0; m1 = mn1;

        const int pp = (gc < 2) ? 4*gc : 4*gc - 7;
        float* pr0 = &QP[arow*FSTR];
        float* pr1 = &QP[(arow+8)*FSTR];
        float s0 = 0.f, s1 = 0.f;
#pragma unroll
        for (int ni = 0; ni < 8; ni++) {
            float p00 = ex2(sc[ni][0] - mn0);
            float p01 = ex2(sc[ni][1] - mn0);
            float p10 = ex2(sc[ni][2] - mn1);
            float p11 = ex2(sc[ni][3] - mn1);
            s0 += p00 + p01;
            s1 += p10 + p11;
            int c = ni*8 + pp;
            pr0[c]   = p00;  pr0[c+2] = p01;
            pr1[c]   = p10;  pr1[c+2] = p11;
        }
        s0 += __shfl_xor_sync(0xffffffffu, s0, 1);
        s0 += __shfl_xor_sync(0xffffffffu, s0, 2);
        s1 += __shfl_xor_sync(0xffffffffu, s1, 1);
        s1 += __shfl_xor_sync(0xffffffffu, s1, 2);
        l0 = l0 * al0 + s0;
        l1 = l1 * al1 + s1;

#pragma unroll
        for (int ni = 0; ni < 8; ni++) {
            o[ni][0] *= al0; o[ni][1] *= al0;
            o[ni][2] *= al1; o[ni][3] *= al1;
        }
        __syncwarp();

#pragma unroll
        for (int ks = 0; ks < 8; ks++) {
            uint2 plo = *(const uint2*)&QP[arow*FSTR + ks*8 + 2*gc];
            uint2 phi = *(const uint2*)&QP[(arow+8)*FSTR + ks*8 + 2*gc];
            unsigned pa[4] = { plo.x, phi.x, plo.y, phi.y };
#pragma unroll
            for (int ni = 0; ni < 8; ni++) {
                unsigned b[2] = { __float_as_uint(Vst[(ks*8 + gc)*FSTR + ni*8 + gr]),
                                  __float_as_uint(Vst[(ks*8 + gc + 4)*FSTR + ni*8 + gr]) };
                mma_tf32(o[ni], pa, b);
            }
        }
    }

    float inv0 = 1.f / l0, inv1 = 1.f / l1;
    const int b = bh / NH_, h = bh % NH_;
    const int srow0 = qt*128 + wid*16 + gr;
#pragma unroll
    for (int ni = 0; ni < 8; ni++) {
        int col = h*64 + ni*8 + 2*gc;
        *(float2*)(g_attn + (size_t)(b*S_ + srow0) * H_ + col) =
            make_float2(__uint_as_float(f2tf32(o[ni][0]*inv0)),
                        __uint_as_float(f2tf32(o[ni][1]*inv0)));
        *(float2*)(g_attn + (size_t)(b*S_ + srow0 + 8) * H_ + col) =
            make_float2(__uint_as_float(f2tf32(o[ni][2]*inv1)),
                        __uint_as_float(f2tf32(o[ni][3]*inv1)));
    }
}

// ---------------- launch --------------------------------------------------------------
extern "C" void kernel_launch(void* const* d_in, const int* in_sizes, int n_in,
                              void* d_out, int out_size) {
    (void)in_sizes; (void)n_in; (void)out_size;
    const float* x       = (const float*)d_in[0];
    const float* ve      = (const float*)d_in[1];
    const float* Wqkv    = (const float*)d_in[2];
    const float* Wo      = (const float*)d_in[3];
    const float* lambdas = (const float*)d_in[4];
    float* out = (float*)d_out;

    void *p_qkv, *p_attn, *p_x32, *p_w1, *p_w2;
    cudaGetSymbolAddress(&p_qkv,  g_qkv);
    cudaGetSymbolAddress(&p_attn, g_attn);
    cudaGetSymbolAddress(&p_x32,  g_x32);
    cudaGetSymbolAddress(&p_w1,   g_w1);
    cudaGetSymbolAddress(&p_w2,   g_w2);

    static bool attr_done = false;
    if (!attr_done) {
        cudaFuncSetAttribute(flash_v6, cudaFuncAttributeMaxDynamicSharedMemorySize,
                             FLASH_SMEM_BYTES);
        cudaFuncSetAttribute(gemm_v8, cudaFuncAttributeMaxDynamicSharedMemorySize,
                             GEMM_SMEM_BYTES);
        attr_done = true;
    }

    // 0) tf32-pre-round GEMM inputs
    cvt_tf32_kernel<<<ROWS_*H_/4/256, 256>>>(x,    (float*)p_x32, ROWS_*H_);
    cvt_tf32_kernel<<<3*H_*H_/4/256,  256>>>(Wqkv, (float*)p_w1,  3*H_*H_);
    cvt_tf32_kernel<<<H_*H_/4/256,    256>>>(Wo,   (float*)p_w2,  H_*H_);
    // 1) qkv = x @ W_qkv^T
    gemm_v8<<<dim3(3*H_/128, ROWS_/128), 256, GEMM_SMEM_BYTES>>>(
        (const float*)p_x32, (const float*)p_w1, (float*)p_qkv, ROWS_, 3*H_, H_);
    // 2) RoPE table
    rope_table_kernel<<<(S_*32 + 255)/256, 256>>>();
    // 3) prep
    prep_kernel<<<(B_*S_*NH_*32 + 255)/256, 256>>>(ve, lambdas);
    // 4) causal flash attention
    flash_v6<<<dim3(S_/128, B_*NH_), 256, FLASH_SMEM_BYTES>>>();
    // 5) out = attn @ W_o^T
    gemm_v8<<<dim3(H_/128, ROWS_/128), 256, GEMM_SMEM_BYTES>>>(
        (const float*)p_attn, (const float*)p_w2, out, ROWS_, H_, H_);
}